// round 5
// baseline (speedup 1.0000x reference)
#include <cuda_runtime.h>
#include <cuda_bf16.h>
#include <cstdint>
#include <math.h>

#define H 256
#define C 512
#define V 32000
#define NB 64
#define T 512

#define CLU 8      // CTAs per cluster
#define CPC 4      // chains per cluster
#define CSL 64     // c' columns per CTA

// ------------------------- static device scratch -------------------------
__device__ float g_startP[C];
__device__ float g_P[C * C];
__device__ float g_fe[C * H];
__device__ float g_L[(size_t)C * V];
__device__ float g_rowmax[C];
__device__ float g_rowinv[C];
__device__ float g_emisT[(size_t)V * C];
__device__ float g_logZ[NB];

// ------------------------------ helpers ------------------------------
__device__ __forceinline__ unsigned long long pk2(float lo, float hi) {
    unsigned long long r;
    asm("mov.b64 %0, {%1, %2};" : "=l"(r) : "f"(lo), "f"(hi));
    return r;
}
__device__ __forceinline__ void upk2(unsigned long long v, float& lo, float& hi) {
    asm("mov.b64 {%0, %1}, %2;" : "=f"(lo), "=f"(hi) : "l"(v));
}
__device__ __forceinline__ unsigned long long fma2(
    unsigned long long a, unsigned long long b, unsigned long long c) {
    unsigned long long d;
    asm("fma.rn.f32x2 %0, %1, %2, %3;" : "=l"(d) : "l"(a), "l"(b), "l"(c));
    return d;
}
__device__ __forceinline__ float warpMax(float v) {
#pragma unroll
    for (int o = 16; o > 0; o >>= 1) v = fmaxf(v, __shfl_xor_sync(0xffffffffu, v, o));
    return v;
}
__device__ __forceinline__ float warpSum(float v) {
#pragma unroll
    for (int o = 16; o > 0; o >>= 1) v += __shfl_xor_sync(0xffffffffu, v, o);
    return v;
}
__device__ __forceinline__ float blockMax256(float v, float* sred) {
    v = warpMax(v);
    int w = threadIdx.x >> 5, ln = threadIdx.x & 31;
    if (ln == 0) sred[w] = v;
    __syncthreads();
    if (w == 0) {
        float x = (ln < 8) ? sred[ln] : -3.4e38f;
        x = warpMax(x);
        if (ln == 0) sred[0] = x;
    }
    __syncthreads();
    float r = sred[0];
    __syncthreads();
    return r;
}
__device__ __forceinline__ float blockSum256(float v, float* sred) {
    v = warpSum(v);
    int w = threadIdx.x >> 5, ln = threadIdx.x & 31;
    if (ln == 0) sred[w] = v;
    __syncthreads();
    if (w == 0) {
        float x = (ln < 8) ? sred[ln] : 0.f;
        x = warpSum(x);
        if (ln == 0) sred[0] = x;
    }
    __syncthreads();
    float r = sred[0];
    __syncthreads();
    return r;
}
__device__ __forceinline__ unsigned smem_u32(const void* p) {
    return (unsigned)__cvta_generic_to_shared(p);
}

#define MBARRIER_INIT_U(addr, cnt) \
    asm volatile("mbarrier.init.shared.b64 [%0], %1;" :: "r"(addr), "r"(cnt) : "memory")

// arrive (release, cluster scope) on the mbarrier at remote address ra
#define MBAR_ARRIVE_REL_CLU(ra) \
    asm volatile("mbarrier.arrive.release.cluster.shared::cluster.b64 _, [%0];" \
                 :: "r"(ra) : "memory")

// wait with acquire at CLUSTER scope (peers' DSMEM stores must become visible)
#define MBAR_WAIT_ACQ_CLU(addr, par) do {                                         \
    unsigned _done;                                                               \
    asm volatile("{\n\t.reg .pred p;\n\t"                                         \
        "mbarrier.try_wait.parity.acquire.cluster.shared::cta.b64 p, [%1], %2;\n\t" \
        "selp.b32 %0, 1, 0, p;\n\t}"                                              \
        : "=r"(_done) : "r"(addr), "r"(par) : "memory");                          \
    if (!_done) {                                                                 \
        asm volatile("{\n\t.reg .pred P1;\n\t"                                    \
            "WL_%=:\n\t"                                                          \
            "mbarrier.try_wait.parity.acquire.cluster.shared::cta.b64 P1, [%0], %1, 0x989680;\n\t" \
            "@P1 bra.uni WD_%=;\n\t"                                              \
            "bra.uni WL_%=;\n\t"                                                  \
            "WD_%=:\n\t}" :: "r"(addr), "r"(par) : "memory");                     \
    }                                                                             \
} while (0)

// ------------------------------ start vector ------------------------------
__global__ __launch_bounds__(256) void start_kernel(
    const float* __restrict__ se, const float* __restrict__ sw,
    const float* __restrict__ sb, const float* __restrict__ rw,
    const float* __restrict__ rb, const float* __restrict__ nse)
{
    __shared__ __align__(16) float x[H];
    __shared__ __align__(16) float h[H];
    __shared__ float sred[32];
    int tid = threadIdx.x;

    x[tid] = se[tid];
    __syncthreads();
    {
        float a = sb[tid];
        for (int k0 = 0; k0 < H; k0 += 8) {
            float w[8];
#pragma unroll
            for (int u = 0; u < 8; ++u) w[u] = sw[(k0 + u) * H + tid];
#pragma unroll
            for (int u = 0; u < 8; ++u) a = fmaf(x[k0 + u], w[u], a);
        }
        __syncthreads();
        x[tid] = a;
        __syncthreads();
    }
    for (int l = 0; l < 2; ++l) {
        const float* w1 = rw + (size_t)(l * 2 + 0) * H * H;
        const float* b1 = rb + (l * 2 + 0) * H;
        const float* w2 = rw + (size_t)(l * 2 + 1) * H * H;
        const float* b2 = rb + (l * 2 + 1) * H;
        float a1 = b1[tid];
        for (int k0 = 0; k0 < H; k0 += 8) {
            float w[8];
#pragma unroll
            for (int u = 0; u < 8; ++u) w[u] = w1[(k0 + u) * H + tid];
#pragma unroll
            for (int u = 0; u < 8; ++u) a1 = fmaf(x[k0 + u], w[u], a1);
        }
        h[tid] = fmaxf(a1, 0.f);
        __syncthreads();
        float a2 = b2[tid];
        for (int k0 = 0; k0 < H; k0 += 8) {
            float w[8];
#pragma unroll
            for (int u = 0; u < 8; ++u) w[u] = w2[(k0 + u) * H + tid];
#pragma unroll
            for (int u = 0; u < 8; ++u) a2 = fmaf(h[k0 + u], w[u], a2);
        }
        __syncthreads();
        x[tid] += fmaxf(a2, 0.f);
        __syncthreads();
    }
    float l0 = 0.f, l1 = 0.f;
    const float4* r0 = (const float4*)(nse + (size_t)tid * H);
    const float4* r1 = (const float4*)(nse + (size_t)(tid + 256) * H);
    const float4* xv4 = (const float4*)x;
#pragma unroll 4
    for (int k4 = 0; k4 < H / 4; ++k4) {
        float4 xa = xv4[k4];
        float4 a = r0[k4], b = r1[k4];
        l0 = fmaf(xa.x, a.x, l0); l0 = fmaf(xa.y, a.y, l0);
        l0 = fmaf(xa.z, a.z, l0); l0 = fmaf(xa.w, a.w, l0);
        l1 = fmaf(xa.x, b.x, l1); l1 = fmaf(xa.y, b.y, l1);
        l1 = fmaf(xa.z, b.z, l1); l1 = fmaf(xa.w, b.w, l1);
    }
    float m = blockMax256(fmaxf(l0, l1), sred);
    float e0 = expf(l0 - m), e1 = expf(l1 - m);
    float s = blockSum256(e0 + e1, sred);
    float inv = 1.f / s;
    g_startP[tid] = e0 * inv;
    g_startP[tid + 256] = e1 * inv;
}

// ------------------------------ terminal MLP ------------------------------
#define TROWS 16
__global__ __launch_bounds__(256) void term_mlp_kernel(
    const float* __restrict__ pre, const float* __restrict__ rw,
    const float* __restrict__ rb)
{
    __shared__ __align__(16) float xs[TROWS][H];
    __shared__ __align__(16) float hs[TROWS][H];
    int r0 = blockIdx.x * TROWS;
    int tid = threadIdx.x;
    for (int i = tid; i < TROWS * H; i += 256)
        xs[i >> 8][i & 255] = pre[(size_t)(r0 + (i >> 8)) * H + (i & 255)];
    __syncthreads();
    for (int l = 0; l < 2; ++l) {
        const float* w1 = rw + (size_t)(l * 2 + 0) * H * H;
        const float* b1 = rb + (l * 2 + 0) * H;
        const float* w2 = rw + (size_t)(l * 2 + 1) * H * H;
        const float* b2 = rb + (l * 2 + 1) * H;
        float acc[TROWS];
#pragma unroll
        for (int r = 0; r < TROWS; ++r) acc[r] = b1[tid];
        for (int k0 = 0; k0 < H; k0 += 8) {
            float w[8];
#pragma unroll
            for (int u = 0; u < 8; ++u) w[u] = w1[(k0 + u) * H + tid];
#pragma unroll
            for (int u = 0; u < 8; ++u)
#pragma unroll
                for (int r = 0; r < TROWS; ++r)
                    acc[r] = fmaf(xs[r][k0 + u], w[u], acc[r]);
        }
#pragma unroll
        for (int r = 0; r < TROWS; ++r) hs[r][tid] = fmaxf(acc[r], 0.f);
        __syncthreads();
#pragma unroll
        for (int r = 0; r < TROWS; ++r) acc[r] = b2[tid];
        for (int k0 = 0; k0 < H; k0 += 8) {
            float w[8];
#pragma unroll
            for (int u = 0; u < 8; ++u) w[u] = w2[(k0 + u) * H + tid];
#pragma unroll
            for (int u = 0; u < 8; ++u)
#pragma unroll
                for (int r = 0; r < TROWS; ++r)
                    acc[r] = fmaf(hs[r][k0 + u], w[u], acc[r]);
        }
        __syncthreads();
#pragma unroll
        for (int r = 0; r < TROWS; ++r) xs[r][tid] += fmaxf(acc[r], 0.f);
        __syncthreads();
    }
    for (int i = tid; i < TROWS * H; i += 256)
        g_fe[(size_t)(r0 + (i >> 8)) * H + (i & 255)] = xs[i >> 8][i & 255];
}

// --------------------- NT GEMM 128x128, 8x8 f32x2 thread tiles ------------
#define GBM 128
#define GBN 128
#define GBK 32
__global__ __launch_bounds__(256) void gemm_nt(
    const float* __restrict__ A, const float* __restrict__ B,
    int dest, int Ncols)
{
    __shared__ __align__(16) float As[GBK][GBM + 1];
    __shared__ __align__(16) float Bs[GBK][GBN + 4];
    float* Cout = dest ? g_L : g_P;
    int bm = blockIdx.y * GBM;
    int bn = blockIdx.x * GBN;
    int tid = threadIdx.x;
    int tm = (tid >> 4) * 8;
    int tn = (tid & 15) * 8;
    unsigned long long acc2[8][4];
#pragma unroll
    for (int i = 0; i < 8; ++i)
#pragma unroll
        for (int j = 0; j < 4; ++j) acc2[i][j] = 0ull;

    for (int k0 = 0; k0 < H; k0 += GBK) {
#pragma unroll
        for (int q = 0; q < 4; ++q) {
            int i = tid + q * 256;
            int m = i >> 3, f = i & 7;
            float4 v = *(const float4*)(A + (size_t)(bm + m) * H + k0 + f * 4);
            As[f * 4 + 0][m] = v.x; As[f * 4 + 1][m] = v.y;
            As[f * 4 + 2][m] = v.z; As[f * 4 + 3][m] = v.w;
        }
#pragma unroll
        for (int q = 0; q < 4; ++q) {
            int i = tid + q * 256;
            int n = i >> 3, f = i & 7;
            float4 v = *(const float4*)(B + (size_t)(bn + n) * H + k0 + f * 4);
            Bs[f * 4 + 0][n] = v.x; Bs[f * 4 + 1][n] = v.y;
            Bs[f * 4 + 2][n] = v.z; Bs[f * 4 + 3][n] = v.w;
        }
        __syncthreads();
#pragma unroll
        for (int kk = 0; kk < GBK; ++kk) {
            unsigned long long ra2[8], rb2[4];
#pragma unroll
            for (int i = 0; i < 8; ++i) {
                float a = As[kk][tm + i];
                ra2[i] = pk2(a, a);
            }
            const unsigned long long* bp = (const unsigned long long*)&Bs[kk][tn];
#pragma unroll
            for (int j = 0; j < 4; ++j) rb2[j] = bp[j];
#pragma unroll
            for (int i = 0; i < 8; ++i)
#pragma unroll
                for (int j = 0; j < 4; ++j)
                    acc2[i][j] = fma2(ra2[i], rb2[j], acc2[i][j]);
        }
        __syncthreads();
    }
#pragma unroll
    for (int i = 0; i < 8; ++i) {
        float c[8];
#pragma unroll
        for (int j = 0; j < 4; ++j) upk2(acc2[i][j], c[2 * j], c[2 * j + 1]);
        *(float4*)(Cout + (size_t)(bm + tm + i) * Ncols + bn + tn) =
            make_float4(c[0], c[1], c[2], c[3]);
        *(float4*)(Cout + (size_t)(bm + tm + i) * Ncols + bn + tn + 4) =
            make_float4(c[4], c[5], c[6], c[7]);
    }
}

// --------------------- transition row softmax ------------------------------
__global__ __launch_bounds__(256) void p_softmax_kernel()
{
    __shared__ float sred[32];
    int c = blockIdx.x;
    int tid = threadIdx.x;
    float* row = g_P + (size_t)c * C;
    float v0 = row[tid], v1 = row[tid + 256];
    float m = blockMax256(fmaxf(v0, v1), sred);
    float e0 = expf(v0 - m), e1 = expf(v1 - m);
    float s = blockSum256(e0 + e1, sred);
    float inv = 1.f / s;
    row[tid] = e0 * inv;
    row[tid + 256] = e1 * inv;
}

// --------------------- emission row stats ----------------------------------
__global__ __launch_bounds__(256) void rowstats_kernel()
{
    __shared__ float sred[32];
    int c = blockIdx.x;
    int tid = threadIdx.x;
    const float4* row = (const float4*)(g_L + (size_t)c * V);
    float mx = -3.4e38f;
    for (int i = tid; i < V / 4; i += 256) {
        float4 v = row[i];
        mx = fmaxf(mx, fmaxf(fmaxf(v.x, v.y), fmaxf(v.z, v.w)));
    }
    float m = blockMax256(mx, sred);
    float s = 0.f;
    for (int i = tid; i < V / 4; i += 256) {
        float4 v = row[i];
        s += expf(v.x - m) + expf(v.y - m) + expf(v.z - m) + expf(v.w - m);
    }
    float tot = blockSum256(s, sred);
    if (tid == 0) {
        g_rowmax[c] = m;
        g_rowinv[c] = 1.f / tot;
    }
}

// --------------------- normalize + transpose to [V][C] ---------------------
__global__ __launch_bounds__(256) void norm_transpose_kernel()
{
    __shared__ float tile[32][33];
    int v0 = blockIdx.x * 32;
    int c0 = blockIdx.y * 32;
    int tid = threadIdx.x;
    int col = tid & 31;
    int rr = tid >> 5;
#pragma unroll
    for (int q = 0; q < 4; ++q) {
        int r = rr + q * 8;
        float l = g_L[(size_t)(c0 + r) * V + v0 + col];
        tile[r][col] = expf(l - g_rowmax[c0 + r]) * g_rowinv[c0 + r];
    }
    __syncthreads();
#pragma unroll
    for (int q = 0; q < 4; ++q) {
        int r = rr + q * 8;
        g_emisT[(size_t)(v0 + r) * C + c0 + col] = tile[col][r];
    }
}

// ------------------------------ HMM scan ------------------------------
__global__ void __cluster_dims__(CLU, 1, 1) __launch_bounds__(256, 1)
scan_kernel(const int* __restrict__ text)
{
    __shared__ __align__(16) float Bf[2][CPC][C];
    __shared__ __align__(16) float part[4][CPC][CSL];
    __shared__ float red[CPC][CSL];
    __shared__ float inv_s[CPC];
    __shared__ float ls_s[CPC];
    __shared__ int toks[2][CPC];
    __shared__ __align__(8) unsigned long long mbar[2];

    const int tid = threadIdx.x;
    const int rank = blockIdx.x & (CLU - 1);
    const int chain0 = (blockIdx.x >> 3) * CPC;
    const int c0 = rank * CSL;
    const int g = tid >> 6;      // K-group 0..3
    const int cl = tid & 63;     // local c'
    const int nn = tid >> 5;     // chain index in 128-thread phases
    const int jj = tid & 31;

    // P slice packed along k (time-invariant, register resident)
    unsigned long long P2[64];
#pragma unroll
    for (int k2 = 0; k2 < 64; ++k2) {
        float lo = g_P[(size_t)(g * 128 + 2 * k2) * C + c0 + cl];
        float hi = g_P[(size_t)(g * 128 + 2 * k2 + 1) * C + c0 + cl];
        P2[k2] = pk2(lo, hi);
    }

    if (tid == 0) {
        MBARRIER_INIT_U(smem_u32(&mbar[0]), CLU);
        MBARRIER_INIT_U(smem_u32(&mbar[1]), CLU);
    }
    if (tid < CPC) {
        toks[0][tid] = text[(chain0 + tid) * T + 0];
        toks[1][tid] = text[(chain0 + tid) * T + 1];
        ls_s[tid] = 0.f;
        inv_s[tid] = 1.f;
    }
    __syncthreads();
    // mbarrier init must be cluster-visible before any peer arrives
    asm volatile("barrier.cluster.arrive.aligned;" ::: "memory");
    asm volatile("barrier.cluster.wait.aligned;" ::: "memory");

    // precompute remote store addresses (epilogue lanes) and mbar addresses
    unsigned dstData[2][CLU];
    {
        unsigned base0 = smem_u32(&Bf[0][0][0]) + (unsigned)((nn * C + c0 + 2 * jj) * 4);
        unsigned base1 = smem_u32(&Bf[1][0][0]) + (unsigned)((nn * C + c0 + 2 * jj) * 4);
#pragma unroll
        for (int r = 0; r < CLU; ++r) {
            asm volatile("mapa.shared::cluster.u32 %0, %1, %2;"
                         : "=r"(dstData[0][r]) : "r"(base0), "r"(r));
            asm volatile("mapa.shared::cluster.u32 %0, %1, %2;"
                         : "=r"(dstData[1][r]) : "r"(base1), "r"(r));
        }
    }
    unsigned mbR[2][CLU];
    {
        unsigned mb0 = smem_u32(&mbar[0]);
        unsigned mb1 = smem_u32(&mbar[1]);
#pragma unroll
        for (int r = 0; r < CLU; ++r) {
            asm volatile("mapa.shared::cluster.u32 %0, %1, %2;"
                         : "=r"(mbR[0][r]) : "r"(mb0), "r"(r));
            asm volatile("mapa.shared::cluster.u32 %0, %1, %2;"
                         : "=r"(mbR[1][r]) : "r"(mb1), "r"(r));
        }
    }

    // alpha0 into Bf[0] (full replicated copy computed locally)
    for (int i = tid; i < CPC * C; i += 256) {
        int n = i >> 9, c = i & (C - 1);
        Bf[0][n][c] = g_startP[c] * g_emisT[(size_t)toks[0][n] * C + c];
    }
    __syncthreads();

    const unsigned mbLocal0 = smem_u32(&mbar[0]);
    const unsigned mbLocal1 = smem_u32(&mbar[1]);

    for (int t = 1; t < T; ++t) {
        const int rb = (t - 1) & 1, wb = t & 1;
        const bool resc = ((t & 3) == 1);

        // prefetches — independent of Bf, issued BEFORE the barrier wait
        float ev0 = 0.f, ev1 = 0.f;
        if (tid < 128) {
            const float2 e2 = *(const float2*)(g_emisT +
                (size_t)toks[wb][nn] * C + c0 + 2 * jj);
            ev0 = e2.x; ev1 = e2.y;
        }
        if (tid >= 252 && t + 1 < T)
            toks[(t + 1) & 1][tid - 252] = text[(chain0 + tid - 252) * T + (t + 1)];

        // wait for all 8 CTAs' slices of Bf[rb] (skip t==1: local init data)
        if (t >= 2) {
            const unsigned mb = rb ? mbLocal1 : mbLocal0;
            const unsigned par = ((t >> 1) - 1) & 1;
            MBAR_WAIT_ACQ_CLU(mb, par);
        }

        // deferred rescale bookkeeping every 4 steps
        if (resc) {
            float mx = 0.f;
#pragma unroll
            for (int j = 0; j < 8; ++j) mx = fmaxf(mx, Bf[rb][g][cl + 64 * j]);
            red[g][cl] = mx;
            __syncthreads();
            if (tid < 128) {
                float v = fmaxf(red[nn][jj], red[nn][jj + 32]);
                v = warpMax(v);
                if (jj == 0) { inv_s[nn] = 1.f / v; ls_s[nn] += logf(v); }
            }
            __syncthreads();
        }

        // packed-FMA partial GEMV over this thread's 128-wide K-chunk, 4 chains
        unsigned long long a0 = 0ull, a1 = 0ull, a2 = 0ull, a3 = 0ull;
        {
            const ulonglong2* r0 = (const ulonglong2*)&Bf[rb][0][g * 128];
            const ulonglong2* r1 = (const ulonglong2*)&Bf[rb][1][g * 128];
            const ulonglong2* r2 = (const ulonglong2*)&Bf[rb][2][g * 128];
            const ulonglong2* r3 = (const ulonglong2*)&Bf[rb][3][g * 128];
#pragma unroll
            for (int k4 = 0; k4 < 32; ++k4) {
                const ulonglong2 v0 = r0[k4], v1 = r1[k4], v2 = r2[k4], v3 = r3[k4];
                const unsigned long long p0 = P2[2 * k4], p1 = P2[2 * k4 + 1];
                a0 = fma2(v0.x, p0, a0); a0 = fma2(v0.y, p1, a0);
                a1 = fma2(v1.x, p0, a1); a1 = fma2(v1.y, p1, a1);
                a2 = fma2(v2.x, p0, a2); a2 = fma2(v2.y, p1, a2);
                a3 = fma2(v3.x, p0, a3); a3 = fma2(v3.y, p1, a3);
            }
        }
        {
            float lo, hi;
            upk2(a0, lo, hi); part[g][0][cl] = lo + hi;
            upk2(a1, lo, hi); part[g][1][cl] = lo + hi;
            upk2(a2, lo, hi); part[g][2][cl] = lo + hi;
            upk2(a3, lo, hi); part[g][3][cl] = lo + hi;
        }
        __syncthreads();

        // reduce K-groups, apply emission (+inv on rescale steps), scatter
        if (tid < 128) {
            const int cc = 2 * jj;
            const float inv = resc ? inv_s[nn] : 1.f;
            float s0 = ((part[0][nn][cc] + part[1][nn][cc]) +
                        (part[2][nn][cc] + part[3][nn][cc])) * (ev0 * inv);
            float s1 = ((part[0][nn][cc + 1] + part[1][nn][cc + 1]) +
                        (part[2][nn][cc + 1] + part[3][nn][cc + 1])) * (ev1 * inv);
            unsigned long long pk = pk2(s0, s1);
#pragma unroll
            for (int r = 0; r < CLU; ++r)
                asm volatile("st.shared::cluster.b64 [%0], %1;"
                             :: "r"(dstData[wb][r]), "l"(pk) : "memory");
        }
        __syncthreads();
        // publish: one release-arrive per peer (covers all this CTA's stores)
        if (tid == 0) {
#pragma unroll
            for (int r = 0; r < CLU; ++r)
                MBAR_ARRIVE_REL_CLU(mbR[wb][r]);
        }
    }

    // wait for the final buffer (Bf[1], written at t=511)
    MBAR_WAIT_ACQ_CLU(mbLocal1, ((T >> 1) - 1) & 1);

    // final: logZ[n] = ls[n] + log(sum_c Bf[1][n][c])
    {
        float sm = 0.f;
#pragma unroll
        for (int j = 0; j < 8; ++j) sm += Bf[(T - 1) & 1][g][cl + 64 * j];
        red[g][cl] = sm;
        __syncthreads();
        if (tid < 128) {
            float v = red[nn][jj] + red[nn][jj + 32];
            v = warpSum(v);
            if (jj == 0 && rank == 0)
                g_logZ[chain0 + nn] = ls_s[nn] + logf(v);
        }
    }
}

// ------------------------------ final reduction ------------------------------
__global__ void final_sum_kernel(float* __restrict__ out)
{
    __shared__ float s[64];
    int tid = threadIdx.x;
    s[tid] = g_logZ[tid];
    __syncthreads();
#pragma unroll
    for (int o = 32; o > 0; o >>= 1) {
        if (tid < o) s[tid] += s[tid + o];
        __syncthreads();
    }
    if (tid == 0) out[0] = s[0];
}

// ------------------------------ launch ------------------------------
extern "C" void kernel_launch(void* const* d_in, const int* in_sizes, int n_in,
                              void* d_out, int out_size)
{
    const int*   text  = (const int*)  d_in[0];
    const float* se    = (const float*)d_in[1];
    const float* sw    = (const float*)d_in[2];
    const float* sb    = (const float*)d_in[3];
    const float* srw   = (const float*)d_in[4];
    const float* srb   = (const float*)d_in[5];
    const float* state = (const float*)d_in[6];
    const float* nse   = (const float*)d_in[7];
    const float* pre   = (const float*)d_in[8];
    const float* trw   = (const float*)d_in[9];
    const float* trb   = (const float*)d_in[10];
    const float* term  = (const float*)d_in[11];
    float* out = (float*)d_out;

    start_kernel<<<1, 256>>>(se, sw, sb, srw, srb, nse);
    gemm_nt<<<dim3(C / GBN, C / GBM), 256>>>(state, nse, /*dest=*/0, C);
    p_softmax_kernel<<<C, 256>>>();
    term_mlp_kernel<<<C / TROWS, 256>>>(pre, trw, trb);
    gemm_nt<<<dim3(V / GBN, C / GBM), 256>>>(g_fe, term, /*dest=*/1, V);
    rowstats_kernel<<<C, 256>>>();
    norm_transpose_kernel<<<dim3(V / 32, C / 32), 256>>>();
    scan_kernel<<<(NB / CPC) * CLU, 256>>>(text);
    final_sum_kernel<<<1, 64>>>(out);
}

// round 6
// speedup vs baseline: 1.0002x; 1.0002x over previous
#include <cuda_runtime.h>
#include <cuda_bf16.h>
#include <cstdint>
#include <math.h>

#define H 256
#define C 512
#define V 32000
#define NB 64
#define T 512

#define CLU 8      // CTAs per cluster
#define CPC 4      // chains per cluster
#define CSL 64     // c' columns per CTA

// ------------------------- static device scratch -------------------------
__device__ float g_startP[C];
__device__ float g_P[C * C];
__device__ float g_fe[C * H];
__device__ float g_L[(size_t)C * V];
__device__ float g_rowmax[C];
__device__ float g_rowinv[C];
__device__ float g_emisT[(size_t)V * C];
__device__ float g_logZ[NB];

// ------------------------------ helpers ------------------------------
__device__ __forceinline__ unsigned long long pk2(float lo, float hi) {
    unsigned long long r;
    asm("mov.b64 %0, {%1, %2};" : "=l"(r) : "f"(lo), "f"(hi));
    return r;
}
__device__ __forceinline__ void upk2(unsigned long long v, float& lo, float& hi) {
    asm("mov.b64 {%0, %1}, %2;" : "=f"(lo), "=f"(hi) : "l"(v));
}
__device__ __forceinline__ unsigned long long fma2(
    unsigned long long a, unsigned long long b, unsigned long long c) {
    unsigned long long d;
    asm("fma.rn.f32x2 %0, %1, %2, %3;" : "=l"(d) : "l"(a), "l"(b), "l"(c));
    return d;
}
__device__ __forceinline__ float warpMax(float v) {
#pragma unroll
    for (int o = 16; o > 0; o >>= 1) v = fmaxf(v, __shfl_xor_sync(0xffffffffu, v, o));
    return v;
}
__device__ __forceinline__ float warpSum(float v) {
#pragma unroll
    for (int o = 16; o > 0; o >>= 1) v += __shfl_xor_sync(0xffffffffu, v, o);
    return v;
}
__device__ __forceinline__ float blockMax256(float v, float* sred) {
    v = warpMax(v);
    int w = threadIdx.x >> 5, ln = threadIdx.x & 31;
    if (ln == 0) sred[w] = v;
    __syncthreads();
    if (w == 0) {
        float x = (ln < 8) ? sred[ln] : -3.4e38f;
        x = warpMax(x);
        if (ln == 0) sred[0] = x;
    }
    __syncthreads();
    float r = sred[0];
    __syncthreads();
    return r;
}
__device__ __forceinline__ float blockSum256(float v, float* sred) {
    v = warpSum(v);
    int w = threadIdx.x >> 5, ln = threadIdx.x & 31;
    if (ln == 0) sred[w] = v;
    __syncthreads();
    if (w == 0) {
        float x = (ln < 8) ? sred[ln] : 0.f;
        x = warpSum(x);
        if (ln == 0) sred[0] = x;
    }
    __syncthreads();
    float r = sred[0];
    __syncthreads();
    return r;
}
__device__ __forceinline__ unsigned smem_u32(const void* p) {
    return (unsigned)__cvta_generic_to_shared(p);
}

#define MBARRIER_INIT_U(addr, cnt) \
    asm volatile("mbarrier.init.shared.b64 [%0], %1;" :: "r"(addr), "r"(cnt) : "memory")

// arrive (release, cluster scope) on the mbarrier at remote address ra
#define MBAR_ARRIVE_REL_CLU(ra) \
    asm volatile("mbarrier.arrive.release.cluster.shared::cluster.b64 _, [%0];" \
                 :: "r"(ra) : "memory")

// wait with acquire at CLUSTER scope (peers' DSMEM stores must become visible)
#define MBAR_WAIT_ACQ_CLU(addr, par) do {                                         \
    unsigned _done;                                                               \
    asm volatile("{\n\t.reg .pred p;\n\t"                                         \
        "mbarrier.try_wait.parity.acquire.cluster.shared::cta.b64 p, [%1], %2;\n\t" \
        "selp.b32 %0, 1, 0, p;\n\t}"                                              \
        : "=r"(_done) : "r"(addr), "r"(par) : "memory");                          \
    if (!_done) {                                                                 \
        asm volatile("{\n\t.reg .pred P1;\n\t"                                    \
            "WL_%=:\n\t"                                                          \
            "mbarrier.try_wait.parity.acquire.cluster.shared::cta.b64 P1, [%0], %1, 0x989680;\n\t" \
            "@P1 bra.uni WD_%=;\n\t"                                              \
            "bra.uni WL_%=;\n\t"                                                  \
            "WD_%=:\n\t}" :: "r"(addr), "r"(par) : "memory");                     \
    }                                                                             \
} while (0)

// ------------------------------ start vector ------------------------------
__global__ __launch_bounds__(256) void start_kernel(
    const float* __restrict__ se, const float* __restrict__ sw,
    const float* __restrict__ sb, const float* __restrict__ rw,
    const float* __restrict__ rb, const float* __restrict__ nse)
{
    __shared__ __align__(16) float x[H];
    __shared__ __align__(16) float h[H];
    __shared__ float sred[32];
    int tid = threadIdx.x;

    x[tid] = se[tid];
    __syncthreads();
    {
        float a = sb[tid];
        for (int k0 = 0; k0 < H; k0 += 8) {
            float w[8];
#pragma unroll
            for (int u = 0; u < 8; ++u) w[u] = sw[(k0 + u) * H + tid];
#pragma unroll
            for (int u = 0; u < 8; ++u) a = fmaf(x[k0 + u], w[u], a);
        }
        __syncthreads();
        x[tid] = a;
        __syncthreads();
    }
    for (int l = 0; l < 2; ++l) {
        const float* w1 = rw + (size_t)(l * 2 + 0) * H * H;
        const float* b1 = rb + (l * 2 + 0) * H;
        const float* w2 = rw + (size_t)(l * 2 + 1) * H * H;
        const float* b2 = rb + (l * 2 + 1) * H;
        float a1 = b1[tid];
        for (int k0 = 0; k0 < H; k0 += 8) {
            float w[8];
#pragma unroll
            for (int u = 0; u < 8; ++u) w[u] = w1[(k0 + u) * H + tid];
#pragma unroll
            for (int u = 0; u < 8; ++u) a1 = fmaf(x[k0 + u], w[u], a1);
        }
        h[tid] = fmaxf(a1, 0.f);
        __syncthreads();
        float a2 = b2[tid];
        for (int k0 = 0; k0 < H; k0 += 8) {
            float w[8];
#pragma unroll
            for (int u = 0; u < 8; ++u) w[u] = w2[(k0 + u) * H + tid];
#pragma unroll
            for (int u = 0; u < 8; ++u) a2 = fmaf(h[k0 + u], w[u], a2);
        }
        __syncthreads();
        x[tid] += fmaxf(a2, 0.f);
        __syncthreads();
    }
    float l0 = 0.f, l1 = 0.f;
    const float4* r0 = (const float4*)(nse + (size_t)tid * H);
    const float4* r1 = (const float4*)(nse + (size_t)(tid + 256) * H);
    const float4* xv4 = (const float4*)x;
#pragma unroll 4
    for (int k4 = 0; k4 < H / 4; ++k4) {
        float4 xa = xv4[k4];
        float4 a = r0[k4], b = r1[k4];
        l0 = fmaf(xa.x, a.x, l0); l0 = fmaf(xa.y, a.y, l0);
        l0 = fmaf(xa.z, a.z, l0); l0 = fmaf(xa.w, a.w, l0);
        l1 = fmaf(xa.x, b.x, l1); l1 = fmaf(xa.y, b.y, l1);
        l1 = fmaf(xa.z, b.z, l1); l1 = fmaf(xa.w, b.w, l1);
    }
    float m = blockMax256(fmaxf(l0, l1), sred);
    float e0 = expf(l0 - m), e1 = expf(l1 - m);
    float s = blockSum256(e0 + e1, sred);
    float inv = 1.f / s;
    g_startP[tid] = e0 * inv;
    g_startP[tid + 256] = e1 * inv;
}

// ------------------------------ terminal MLP ------------------------------
#define TROWS 16
__global__ __launch_bounds__(256) void term_mlp_kernel(
    const float* __restrict__ pre, const float* __restrict__ rw,
    const float* __restrict__ rb)
{
    __shared__ __align__(16) float xs[TROWS][H];
    __shared__ __align__(16) float hs[TROWS][H];
    int r0 = blockIdx.x * TROWS;
    int tid = threadIdx.x;
    for (int i = tid; i < TROWS * H; i += 256)
        xs[i >> 8][i & 255] = pre[(size_t)(r0 + (i >> 8)) * H + (i & 255)];
    __syncthreads();
    for (int l = 0; l < 2; ++l) {
        const float* w1 = rw + (size_t)(l * 2 + 0) * H * H;
        const float* b1 = rb + (l * 2 + 0) * H;
        const float* w2 = rw + (size_t)(l * 2 + 1) * H * H;
        const float* b2 = rb + (l * 2 + 1) * H;
        float acc[TROWS];
#pragma unroll
        for (int r = 0; r < TROWS; ++r) acc[r] = b1[tid];
        for (int k0 = 0; k0 < H; k0 += 8) {
            float w[8];
#pragma unroll
            for (int u = 0; u < 8; ++u) w[u] = w1[(k0 + u) * H + tid];
#pragma unroll
            for (int u = 0; u < 8; ++u)
#pragma unroll
                for (int r = 0; r < TROWS; ++r)
                    acc[r] = fmaf(xs[r][k0 + u], w[u], acc[r]);
        }
#pragma unroll
        for (int r = 0; r < TROWS; ++r) hs[r][tid] = fmaxf(acc[r], 0.f);
        __syncthreads();
#pragma unroll
        for (int r = 0; r < TROWS; ++r) acc[r] = b2[tid];
        for (int k0 = 0; k0 < H; k0 += 8) {
            float w[8];
#pragma unroll
            for (int u = 0; u < 8; ++u) w[u] = w2[(k0 + u) * H + tid];
#pragma unroll
            for (int u = 0; u < 8; ++u)
#pragma unroll
                for (int r = 0; r < TROWS; ++r)
                    acc[r] = fmaf(hs[r][k0 + u], w[u], acc[r]);
        }
        __syncthreads();
#pragma unroll
        for (int r = 0; r < TROWS; ++r) xs[r][tid] += fmaxf(acc[r], 0.f);
        __syncthreads();
    }
    for (int i = tid; i < TROWS * H; i += 256)
        g_fe[(size_t)(r0 + (i >> 8)) * H + (i & 255)] = xs[i >> 8][i & 255];
}

// --------------------- NT GEMM 128x128, 8x8 f32x2 thread tiles ------------
#define GBM 128
#define GBN 128
#define GBK 32
__global__ __launch_bounds__(256) void gemm_nt(
    const float* __restrict__ A, const float* __restrict__ B,
    int dest, int Ncols)
{
    __shared__ __align__(16) float As[GBK][GBM + 1];
    __shared__ __align__(16) float Bs[GBK][GBN + 4];
    float* Cout = dest ? g_L : g_P;
    int bm = blockIdx.y * GBM;
    int bn = blockIdx.x * GBN;
    int tid = threadIdx.x;
    int tm = (tid >> 4) * 8;
    int tn = (tid & 15) * 8;
    unsigned long long acc2[8][4];
#pragma unroll
    for (int i = 0; i < 8; ++i)
#pragma unroll
        for (int j = 0; j < 4; ++j) acc2[i][j] = 0ull;

    for (int k0 = 0; k0 < H; k0 += GBK) {
#pragma unroll
        for (int q = 0; q < 4; ++q) {
            int i = tid + q * 256;
            int m = i >> 3, f = i & 7;
            float4 v = *(const float4*)(A + (size_t)(bm + m) * H + k0 + f * 4);
            As[f * 4 + 0][m] = v.x; As[f * 4 + 1][m] = v.y;
            As[f * 4 + 2][m] = v.z; As[f * 4 + 3][m] = v.w;
        }
#pragma unroll
        for (int q = 0; q < 4; ++q) {
            int i = tid + q * 256;
            int n = i >> 3, f = i & 7;
            float4 v = *(const float4*)(B + (size_t)(bn + n) * H + k0 + f * 4);
            Bs[f * 4 + 0][n] = v.x; Bs[f * 4 + 1][n] = v.y;
            Bs[f * 4 + 2][n] = v.z; Bs[f * 4 + 3][n] = v.w;
        }
        __syncthreads();
#pragma unroll
        for (int kk = 0; kk < GBK; ++kk) {
            unsigned long long ra2[8], rb2[4];
#pragma unroll
            for (int i = 0; i < 8; ++i) {
                float a = As[kk][tm + i];
                ra2[i] = pk2(a, a);
            }
            const unsigned long long* bp = (const unsigned long long*)&Bs[kk][tn];
#pragma unroll
            for (int j = 0; j < 4; ++j) rb2[j] = bp[j];
#pragma unroll
            for (int i = 0; i < 8; ++i)
#pragma unroll
                for (int j = 0; j < 4; ++j)
                    acc2[i][j] = fma2(ra2[i], rb2[j], acc2[i][j]);
        }
        __syncthreads();
    }
#pragma unroll
    for (int i = 0; i < 8; ++i) {
        float c[8];
#pragma unroll
        for (int j = 0; j < 4; ++j) upk2(acc2[i][j], c[2 * j], c[2 * j + 1]);
        *(float4*)(Cout + (size_t)(bm + tm + i) * Ncols + bn + tn) =
            make_float4(c[0], c[1], c[2], c[3]);
        *(float4*)(Cout + (size_t)(bm + tm + i) * Ncols + bn + tn + 4) =
            make_float4(c[4], c[5], c[6], c[7]);
    }
}

// --------------------- transition row softmax ------------------------------
__global__ __launch_bounds__(256) void p_softmax_kernel()
{
    __shared__ float sred[32];
    int c = blockIdx.x;
    int tid = threadIdx.x;
    float* row = g_P + (size_t)c * C;
    float v0 = row[tid], v1 = row[tid + 256];
    float m = blockMax256(fmaxf(v0, v1), sred);
    float e0 = expf(v0 - m), e1 = expf(v1 - m);
    float s = blockSum256(e0 + e1, sred);
    float inv = 1.f / s;
    row[tid] = e0 * inv;
    row[tid + 256] = e1 * inv;
}

// --------------------- emission row stats ----------------------------------
__global__ __launch_bounds__(256) void rowstats_kernel()
{
    __shared__ float sred[32];
    int c = blockIdx.x;
    int tid = threadIdx.x;
    const float4* row = (const float4*)(g_L + (size_t)c * V);
    float mx = -3.4e38f;
    for (int i = tid; i < V / 4; i += 256) {
        float4 v = row[i];
        mx = fmaxf(mx, fmaxf(fmaxf(v.x, v.y), fmaxf(v.z, v.w)));
    }
    float m = blockMax256(mx, sred);
    float s = 0.f;
    for (int i = tid; i < V / 4; i += 256) {
        float4 v = row[i];
        s += expf(v.x - m) + expf(v.y - m) + expf(v.z - m) + expf(v.w - m);
    }
    float tot = blockSum256(s, sred);
    if (tid == 0) {
        g_rowmax[c] = m;
        g_rowinv[c] = 1.f / tot;
    }
}

// --------------------- normalize + transpose to [V][C] ---------------------
__global__ __launch_bounds__(256) void norm_transpose_kernel()
{
    __shared__ float tile[32][33];
    int v0 = blockIdx.x * 32;
    int c0 = blockIdx.y * 32;
    int tid = threadIdx.x;
    int col = tid & 31;
    int rr = tid >> 5;
#pragma unroll
    for (int q = 0; q < 4; ++q) {
        int r = rr + q * 8;
        float l = g_L[(size_t)(c0 + r) * V + v0 + col];
        tile[r][col] = expf(l - g_rowmax[c0 + r]) * g_rowinv[c0 + r];
    }
    __syncthreads();
#pragma unroll
    for (int q = 0; q < 4; ++q) {
        int r = rr + q * 8;
        g_emisT[(size_t)(v0 + r) * C + c0 + col] = tile[col][r];
    }
}

// ------------------------------ HMM scan ------------------------------
__global__ void __cluster_dims__(CLU, 1, 1) __launch_bounds__(256, 1)
scan_kernel(const int* __restrict__ text)
{
    __shared__ __align__(16) float Bf[2][CPC][C];
    __shared__ __align__(16) float part[4][CPC][CSL];
    __shared__ float red[CPC][CSL];
    __shared__ float inv_s[CPC];
    __shared__ float ls_s[CPC];
    __shared__ int toks[2][CPC];
    __shared__ __align__(8) unsigned long long mbar[2];

    const int tid = threadIdx.x;
    const int rank = blockIdx.x & (CLU - 1);
    const int chain0 = (blockIdx.x >> 3) * CPC;
    const int c0 = rank * CSL;
    const int g = tid >> 6;      // K-group 0..3
    const int cl = tid & 63;     // local c'
    const int nn = tid >> 5;     // chain index in 128-thread phases
    const int jj = tid & 31;

    // P slice packed along k (time-invariant, register resident)
    unsigned long long P2[64];
#pragma unroll
    for (int k2 = 0; k2 < 64; ++k2) {
        float lo = g_P[(size_t)(g * 128 + 2 * k2) * C + c0 + cl];
        float hi = g_P[(size_t)(g * 128 + 2 * k2 + 1) * C + c0 + cl];
        P2[k2] = pk2(lo, hi);
    }

    if (tid == 0) {
        MBARRIER_INIT_U(smem_u32(&mbar[0]), CLU);
        MBARRIER_INIT_U(smem_u32(&mbar[1]), CLU);
    }
    if (tid < CPC) {
        toks[0][tid] = text[(chain0 + tid) * T + 0];
        toks[1][tid] = text[(chain0 + tid) * T + 1];
        ls_s[tid] = 0.f;
        inv_s[tid] = 1.f;
    }
    __syncthreads();
    // mbarrier init must be cluster-visible before any peer arrives
    asm volatile("barrier.cluster.arrive.aligned;" ::: "memory");
    asm volatile("barrier.cluster.wait.aligned;" ::: "memory");

    // precompute remote store addresses (epilogue lanes) and mbar addresses
    unsigned dstData[2][CLU];
    {
        unsigned base0 = smem_u32(&Bf[0][0][0]) + (unsigned)((nn * C + c0 + 2 * jj) * 4);
        unsigned base1 = smem_u32(&Bf[1][0][0]) + (unsigned)((nn * C + c0 + 2 * jj) * 4);
#pragma unroll
        for (int r = 0; r < CLU; ++r) {
            asm volatile("mapa.shared::cluster.u32 %0, %1, %2;"
                         : "=r"(dstData[0][r]) : "r"(base0), "r"(r));
            asm volatile("mapa.shared::cluster.u32 %0, %1, %2;"
                         : "=r"(dstData[1][r]) : "r"(base1), "r"(r));
        }
    }
    unsigned mbR[2][CLU];
    {
        unsigned mb0 = smem_u32(&mbar[0]);
        unsigned mb1 = smem_u32(&mbar[1]);
#pragma unroll
        for (int r = 0; r < CLU; ++r) {
            asm volatile("mapa.shared::cluster.u32 %0, %1, %2;"
                         : "=r"(mbR[0][r]) : "r"(mb0), "r"(r));
            asm volatile("mapa.shared::cluster.u32 %0, %1, %2;"
                         : "=r"(mbR[1][r]) : "r"(mb1), "r"(r));
        }
    }

    // alpha0 into Bf[0] (full replicated copy computed locally)
    for (int i = tid; i < CPC * C; i += 256) {
        int n = i >> 9, c = i & (C - 1);
        Bf[0][n][c] = g_startP[c] * g_emisT[(size_t)toks[0][n] * C + c];
    }
    __syncthreads();

    const unsigned mbLocal0 = smem_u32(&mbar[0]);
    const unsigned mbLocal1 = smem_u32(&mbar[1]);

    for (int t = 1; t < T; ++t) {
        const int rb = (t - 1) & 1, wb = t & 1;
        const bool resc = ((t & 3) == 1);

        // prefetches — independent of Bf, issued BEFORE the barrier wait
        float ev0 = 0.f, ev1 = 0.f;
        if (tid < 128) {
            const float2 e2 = *(const float2*)(g_emisT +
                (size_t)toks[wb][nn] * C + c0 + 2 * jj);
            ev0 = e2.x; ev1 = e2.y;
        }
        if (tid >= 252 && t + 1 < T)
            toks[(t + 1) & 1][tid - 252] = text[(chain0 + tid - 252) * T + (t + 1)];

        // wait for all 8 CTAs' slices of Bf[rb] (skip t==1: local init data)
        if (t >= 2) {
            const unsigned mb = rb ? mbLocal1 : mbLocal0;
            const unsigned par = ((t >> 1) - 1) & 1;
            MBAR_WAIT_ACQ_CLU(mb, par);
        }

        // deferred rescale bookkeeping every 4 steps
        if (resc) {
            float mx = 0.f;
#pragma unroll
            for (int j = 0; j < 8; ++j) mx = fmaxf(mx, Bf[rb][g][cl + 64 * j]);
            red[g][cl] = mx;
            __syncthreads();
            if (tid < 128) {
                float v = fmaxf(red[nn][jj], red[nn][jj + 32]);
                v = warpMax(v);
                if (jj == 0) { inv_s[nn] = 1.f / v; ls_s[nn] += logf(v); }
            }
            __syncthreads();
        }

        // packed-FMA partial GEMV over this thread's 128-wide K-chunk, 4 chains
        unsigned long long a0 = 0ull, a1 = 0ull, a2 = 0ull, a3 = 0ull;
        {
            const ulonglong2* r0 = (const ulonglong2*)&Bf[rb][0][g * 128];
            const ulonglong2* r1 = (const ulonglong2*)&Bf[rb][1][g * 128];
            const ulonglong2* r2 = (const ulonglong2*)&Bf[rb][2][g * 128];
            const ulonglong2* r3 = (const ulonglong2*)&Bf[rb][3][g * 128];
#pragma unroll
            for (int k4 = 0; k4 < 32; ++k4) {
                const ulonglong2 v0 = r0[k4], v1 = r1[k4], v2 = r2[k4], v3 = r3[k4];
                const unsigned long long p0 = P2[2 * k4], p1 = P2[2 * k4 + 1];
                a0 = fma2(v0.x, p0, a0); a0 = fma2(v0.y, p1, a0);
                a1 = fma2(v1.x, p0, a1); a1 = fma2(v1.y, p1, a1);
                a2 = fma2(v2.x, p0, a2); a2 = fma2(v2.y, p1, a2);
                a3 = fma2(v3.x, p0, a3); a3 = fma2(v3.y, p1, a3);
            }
        }
        {
            float lo, hi;
            upk2(a0, lo, hi); part[g][0][cl] = lo + hi;
            upk2(a1, lo, hi); part[g][1][cl] = lo + hi;
            upk2(a2, lo, hi); part[g][2][cl] = lo + hi;
            upk2(a3, lo, hi); part[g][3][cl] = lo + hi;
        }
        __syncthreads();

        // reduce K-groups, apply emission (+inv on rescale steps), scatter
        if (tid < 128) {
            const int cc = 2 * jj;
            const float inv = resc ? inv_s[nn] : 1.f;
            float s0 = ((part[0][nn][cc] + part[1][nn][cc]) +
                        (part[2][nn][cc] + part[3][nn][cc])) * (ev0 * inv);
            float s1 = ((part[0][nn][cc + 1] + part[1][nn][cc + 1]) +
                        (part[2][nn][cc + 1] + part[3][nn][cc + 1])) * (ev1 * inv);
            unsigned long long pk = pk2(s0, s1);
#pragma unroll
            for (int r = 0; r < CLU; ++r)
                asm volatile("st.shared::cluster.b64 [%0], %1;"
                             :: "r"(dstData[wb][r]), "l"(pk) : "memory");
        }
        __syncthreads();
        // publish: one release-arrive per peer (covers all this CTA's stores)
        if (tid == 0) {
#pragma unroll
            for (int r = 0; r < CLU; ++r)
                MBAR_ARRIVE_REL_CLU(mbR[wb][r]);
        }
    }

    // wait for the final buffer (Bf[1], written at t=511)
    MBAR_WAIT_ACQ_CLU(mbLocal1, ((T >> 1) - 1) & 1);

    // final: logZ[n] = ls[n] + log(sum_c Bf[1][n][c])
    {
        float sm = 0.f;
#pragma unroll
        for (int j = 0; j < 8; ++j) sm += Bf[(T - 1) & 1][g][cl + 64 * j];
        red[g][cl] = sm;
        __syncthreads();
        if (tid < 128) {
            float v = red[nn][jj] + red[nn][jj + 32];
            v = warpSum(v);
            if (jj == 0 && rank == 0)
                g_logZ[chain0 + nn] = ls_s[nn] + logf(v);
        }
    }
}

// ------------------------------ final reduction ------------------------------
__global__ void final_sum_kernel(float* __restrict__ out)
{
    __shared__ float s[64];
    int tid = threadIdx.x;
    s[tid] = g_logZ[tid];
    __syncthreads();
#pragma unroll
    for (int o = 32; o > 0; o >>= 1) {
        if (tid < o) s[tid] += s[tid + o];
        __syncthreads();
    }
    if (tid == 0) out[0] = s[0];
}

// ------------------------------ launch ------------------------------
extern "C" void kernel_launch(void* const* d_in, const int* in_sizes, int n_in,
                              void* d_out, int out_size)
{
    const int*   text  = (const int*)  d_in[0];
    const float* se    = (const float*)d_in[1];
    const float* sw    = (const float*)d_in[2];
    const float* sb    = (const float*)d_in[3];
    const float* srw   = (const float*)d_in[4];
    const float* srb   = (const float*)d_in[5];
    const float* state = (const float*)d_in[6];
    const float* nse   = (const float*)d_in[7];
    const float* pre   = (const float*)d_in[8];
    const float* trw   = (const float*)d_in[9];
    const float* trb   = (const float*)d_in[10];
    const float* term  = (const float*)d_in[11];
    float* out = (float*)d_out;

    start_kernel<<<1, 256>>>(se, sw, sb, srw, srb, nse);
    gemm_nt<<<dim3(C / GBN, C / GBM), 256>>>(state, nse, /*dest=*/0, C);
    p_softmax_kernel<<<C, 256>>>();
    term_mlp_kernel<<<C / TROWS, 256>>>(pre, trw, trb);
    gemm_nt<<<dim3(V / GBN, C / GBM), 256>>>(g_fe, term, /*dest=*/1, V);
    rowstats_kernel<<<C, 256>>>();
    norm_transpose_kernel<<<dim3(V / 32, C / 32), 256>>>();
    scan_kernel<<<(NB / CPC) * CLU, 256>>>(text);
    final_sum_kernel<<<1, 64>>>(out);
}

// round 7
// speedup vs baseline: 1.4672x; 1.4669x over previous
#include <cuda_runtime.h>
#include <cuda_bf16.h>
#include <cstdint>
#include <math.h>

#define H 256
#define C 512
#define V 32000
#define NB 64
#define T 512

#define CLU 8
#define CPC 4
#define CSL 64

__device__ float g_startP[C];
__device__ float g_P[C * C];
__device__ float g_fe[C * H];
__device__ float g_L[(size_t)C * V];
__device__ float g_rowmax[C];
__device__ float g_rowinv[C];
__device__ float g_emisT[(size_t)V * C];
__device__ float g_logZ[NB];

__device__ __forceinline__ unsigned long long pk2(float lo, float hi) {
    unsigned long long r;
    asm("mov.b64 %0, {%1, %2};" : "=l"(r) : "f"(lo), "f"(hi));
    return r;
}
__device__ __forceinline__ void upk2(unsigned long long v, float& lo, float& hi) {
    asm("mov.b64 {%0, %1}, %2;" : "=f"(lo), "=f"(hi) : "l"(v));
}
__device__ __forceinline__ unsigned long long fma2(
    unsigned long long a, unsigned long long b, unsigned long long c) {
    unsigned long long d;
    asm("fma.rn.f32x2 %0, %1, %2, %3;" : "=l"(d) : "l"(a), "l"(b), "l"(c));
    return d;
}
__device__ __forceinline__ float warpMax(float v) {
#pragma unroll
    for (int o = 16; o > 0; o >>= 1) v = fmaxf(v, __shfl_xor_sync(0xffffffffu, v, o));
    return v;
}
__device__ __forceinline__ float warpSum(float v) {
#pragma unroll
    for (int o = 16; o > 0; o >>= 1) v += __shfl_xor_sync(0xffffffffu, v, o);
    return v;
}
__device__ __forceinline__ float blockMax256(float v, float* sred) {
    v = warpMax(v);
    int w = threadIdx.x >> 5, ln = threadIdx.x & 31;
    if (ln == 0) sred[w] = v;
    __syncthreads();
    if (w == 0) {
        float x = (ln < 8) ? sred[ln] : -3.4e38f;
        x = warpMax(x);
        if (ln == 0) sred[0] = x;
    }
    __syncthreads();
    float r = sred[0];
    __syncthreads();
    return r;
}
__device__ __forceinline__ float blockSum256(float v, float* sred) {
    v = warpSum(v);
    int w = threadIdx.x >> 5, ln = threadIdx.x & 31;
    if (ln == 0) sred[w] = v;
    __syncthreads();
    if (w == 0) {
        float x = (ln < 8) ? sred[ln] : 0.f;
        x = warpSum(x);
        if (ln == 0) sred[0] = x;
    }
    __syncthreads();
    float r = sred[0];
    __syncthreads();
    return r;
}
__device__ __forceinline__ unsigned smem_u32(const void* p) {
    return (unsigned)__cvta_generic_to_shared(p);
}

// ------------------------------ start vector ------------------------------
__global__ __launch_bounds__(256) void start_kernel(
    const float* __restrict__ se, const float* __restrict__ sw,
    const float* __restrict__ sb, const float* __restrict__ rw,
    const float* __restrict__ rb, const float* __restrict__ nse)
{
    __shared__ __align__(16) float x[H];
    __shared__ __align__(16) float h[H];
    __shared__ float sred[32];
    int tid = threadIdx.x;

    x[tid] = se[tid];
    __syncthreads();
    {
        float a = sb[tid];
        for (int k0 = 0; k0 < H; k0 += 8) {
            float w[8];
#pragma unroll
            for (int u = 0; u < 8; ++u) w[u] = sw[(k0 + u) * H + tid];
#pragma unroll
            for (int u = 0; u < 8; ++u) a = fmaf(x[k0 + u], w[u], a);
        }
        __syncthreads();
        x[tid] = a;
        __syncthreads();
    }
    for (int l = 0; l < 2; ++l) {
        const float* w1 = rw + (size_t)(l * 2 + 0) * H * H;
        const float* b1 = rb + (l * 2 + 0) * H;
        const float* w2 = rw + (size_t)(l * 2 + 1) * H * H;
        const float* b2 = rb + (l * 2 + 1) * H;
        float a1 = b1[tid];
        for (int k0 = 0; k0 < H; k0 += 8) {
            float w[8];
#pragma unroll
            for (int u = 0; u < 8; ++u) w[u] = w1[(k0 + u) * H + tid];
#pragma unroll
            for (int u = 0; u < 8; ++u) a1 = fmaf(x[k0 + u], w[u], a1);
        }
        h[tid] = fmaxf(a1, 0.f);
        __syncthreads();
        float a2 = b2[tid];
        for (int k0 = 0; k0 < H; k0 += 8) {
            float w[8];
#pragma unroll
            for (int u = 0; u < 8; ++u) w[u] = w2[(k0 + u) * H + tid];
#pragma unroll
            for (int u = 0; u < 8; ++u) a2 = fmaf(h[k0 + u], w[u], a2);
        }
        __syncthreads();
        x[tid] += fmaxf(a2, 0.f);
        __syncthreads();
    }
    float l0 = 0.f, l1 = 0.f;
    const float4* r0 = (const float4*)(nse + (size_t)tid * H);
    const float4* r1 = (const float4*)(nse + (size_t)(tid + 256) * H);
    const float4* xv4 = (const float4*)x;
#pragma unroll 4
    for (int k4 = 0; k4 < H / 4; ++k4) {
        float4 xa = xv4[k4];
        float4 a = r0[k4], b = r1[k4];
        l0 = fmaf(xa.x, a.x, l0); l0 = fmaf(xa.y, a.y, l0);
        l0 = fmaf(xa.z, a.z, l0); l0 = fmaf(xa.w, a.w, l0);
        l1 = fmaf(xa.x, b.x, l1); l1 = fmaf(xa.y, b.y, l1);
        l1 = fmaf(xa.z, b.z, l1); l1 = fmaf(xa.w, b.w, l1);
    }
    float m = blockMax256(fmaxf(l0, l1), sred);
    float e0 = expf(l0 - m), e1 = expf(l1 - m);
    float s = blockSum256(e0 + e1, sred);
    float inv = 1.f / s;
    g_startP[tid] = e0 * inv;
    g_startP[tid + 256] = e1 * inv;
}

// ------------------------------ terminal MLP ------------------------------
#define TROWS 4
__global__ __launch_bounds__(256) void term_mlp_kernel(
    const float* __restrict__ pre, const float* __restrict__ rw,
    const float* __restrict__ rb)
{
    __shared__ __align__(16) float xs[TROWS][H];
    __shared__ __align__(16) float hs[TROWS][H];
    int r0 = blockIdx.x * TROWS;
    int tid = threadIdx.x;
    for (int i = tid; i < TROWS * H; i += 256)
        xs[i >> 8][i & 255] = pre[(size_t)(r0 + (i >> 8)) * H + (i & 255)];
    __syncthreads();
    for (int l = 0; l < 2; ++l) {
        const float* w1 = rw + (size_t)(l * 2 + 0) * H * H;
        const float* b1 = rb + (l * 2 + 0) * H;
        const float* w2 = rw + (size_t)(l * 2 + 1) * H * H;
        const float* b2 = rb + (l * 2 + 1) * H;
        float acc[TROWS];
#pragma unroll
        for (int r = 0; r < TROWS; ++r) acc[r] = b1[tid];
        for (int k0 = 0; k0 < H; k0 += 16) {
            float w[16];
#pragma unroll
            for (int u = 0; u < 16; ++u) w[u] = w1[(k0 + u) * H + tid];
#pragma unroll
            for (int u = 0; u < 16; ++u)
#pragma unroll
                for (int r = 0; r < TROWS; ++r)
                    acc[r] = fmaf(xs[r][k0 + u], w[u], acc[r]);
        }
#pragma unroll
        for (int r = 0; r < TROWS; ++r) hs[r][tid] = fmaxf(acc[r], 0.f);
        __syncthreads();
#pragma unroll
        for (int r = 0; r < TROWS; ++r) acc[r] = b2[tid];
        for (int k0 = 0; k0 < H; k0 += 16) {
            float w[16];
#pragma unroll
            for (int u = 0; u < 16; ++u) w[u] = w2[(k0 + u) * H + tid];
#pragma unroll
            for (int u = 0; u < 16; ++u)
#pragma unroll
                for (int r = 0; r < TROWS; ++r)
                    acc[r] = fmaf(hs[r][k0 + u], w[u], acc[r]);
        }
        __syncthreads();
#pragma unroll
        for (int r = 0; r < TROWS; ++r) xs[r][tid] += fmaxf(acc[r], 0.f);
        __syncthreads();
    }
    for (int i = tid; i < TROWS * H; i += 256)
        g_fe[(size_t)(r0 + (i >> 8)) * H + (i & 255)] = xs[i >> 8][i & 255];
}

// --------------------- NT GEMM (proven R3 config) --------------------------
#define GBM 64
#define GBN 128
#define GBK 32
__global__ __launch_bounds__(256) void gemm_nt(
    const float* __restrict__ A, const float* __restrict__ B,
    int dest, int Ncols)
{
    __shared__ __align__(16) float As[GBK][GBM + 1];
    __shared__ __align__(16) float Bs[GBK][GBN + 4];
    float* Cout = dest ? g_L : g_P;
    int bm = blockIdx.y * GBM;
    int bn = blockIdx.x * GBN;
    int tid = threadIdx.x;
    int tm = (tid >> 4) * 4;
    int tn = (tid & 15) * 8;
    unsigned long long acc2[4][4];
#pragma unroll
    for (int i = 0; i < 4; ++i)
#pragma unroll
        for (int j = 0; j < 4; ++j) acc2[i][j] = 0ull;

    for (int k0 = 0; k0 < H; k0 += GBK) {
#pragma unroll
        for (int q = 0; q < 2; ++q) {
            int i = tid + q * 256;
            int m = i >> 3, f = i & 7;
            float4 v = *(const float4*)(A + (size_t)(bm + m) * H + k0 + f * 4);
            As[f * 4 + 0][m] = v.x; As[f * 4 + 1][m] = v.y;
            As[f * 4 + 2][m] = v.z; As[f * 4 + 3][m] = v.w;
        }
#pragma unroll
        for (int q = 0; q < 4; ++q) {
            int i = tid + q * 256;
            int n = i >> 3, f = i & 7;
            float4 v = *(const float4*)(B + (size_t)(bn + n) * H + k0 + f * 4);
            Bs[f * 4 + 0][n] = v.x; Bs[f * 4 + 1][n] = v.y;
            Bs[f * 4 + 2][n] = v.z; Bs[f * 4 + 3][n] = v.w;
        }
        __syncthreads();
#pragma unroll
        for (int kk = 0; kk < GBK; ++kk) {
            unsigned long long ra2[4], rb2[4];
#pragma unroll
            for (int i = 0; i < 4; ++i) {
                float a = As[kk][tm + i];
                ra2[i] = pk2(a, a);
            }
            const unsigned long long* bp = (const unsigned long long*)&Bs[kk][tn];
#pragma unroll
            for (int j = 0; j < 4; ++j) rb2[j] = bp[j];
#pragma unroll
            for (int i = 0; i < 4; ++i)
#pragma unroll
                for (int j = 0; j < 4; ++j)
                    acc2[i][j] = fma2(ra2[i], rb2[j], acc2[i][j]);
        }
        __syncthreads();
    }
#pragma unroll
    for (int i = 0; i < 4; ++i) {
        float c[8];
#pragma unroll
        for (int j = 0; j < 4; ++j) upk2(acc2[i][j], c[2 * j], c[2 * j + 1]);
        *(float4*)(Cout + (size_t)(bm + tm + i) * Ncols + bn + tn) =
            make_float4(c[0], c[1], c[2], c[3]);
        *(float4*)(Cout + (size_t)(bm + tm + i) * Ncols + bn + tn + 4) =
            make_float4(c[4], c[5], c[6], c[7]);
    }
}

__global__ __launch_bounds__(256) void p_softmax_kernel()
{
    __shared__ float sred[32];
    int c = blockIdx.x;
    int tid = threadIdx.x;
    float* row = g_P + (size_t)c * C;
    float v0 = row[tid], v1 = row[tid + 256];
    float m = blockMax256(fmaxf(v0, v1), sred);
    float e0 = expf(v0 - m), e1 = expf(v1 - m);
    float s = blockSum256(e0 + e1, sred);
    float inv = 1.f / s;
    row[tid] = e0 * inv;
    row[tid + 256] = e1 * inv;
}

__global__ __launch_bounds__(256) void rowstats_kernel()
{
    __shared__ float sred[32];
    int c = blockIdx.x;
    int tid = threadIdx.x;
    const float4* row = (const float4*)(g_L + (size_t)c * V);
    float mx = -3.4e38f;
    for (int i = tid; i < V / 4; i += 256) {
        float4 v = row[i];
        mx = fmaxf(mx, fmaxf(fmaxf(v.x, v.y), fmaxf(v.z, v.w)));
    }
    float m = blockMax256(mx, sred);
    float s = 0.f;
    for (int i = tid; i < V / 4; i += 256) {
        float4 v = row[i];
        s += expf(v.x - m) + expf(v.y - m) + expf(v.z - m) + expf(v.w - m);
    }
    float tot = blockSum256(s, sred);
    if (tid == 0) {
        g_rowmax[c] = m;
        g_rowinv[c] = 1.f / tot;
    }
}

__global__ __launch_bounds__(256) void norm_transpose_kernel()
{
    __shared__ float tile[32][33];
    int v0 = blockIdx.x * 32;
    int c0 = blockIdx.y * 32;
    int tid = threadIdx.x;
    int col = tid & 31;
    int rr = tid >> 5;
#pragma unroll
    for (int q = 0; q < 4; ++q) {
        int r = rr + q * 8;
        float l = g_L[(size_t)(c0 + r) * V + v0 + col];
        tile[r][col] = expf(l - g_rowmax[c0 + r]) * g_rowinv[c0 + r];
    }
    __syncthreads();
#pragma unroll
    for (int q = 0; q < 4; ++q) {
        int r = rr + q * 8;
        g_emisT[(size_t)(v0 + r) * C + c0 + col] = tile[col][r];
    }
}

// ------------------------------ HMM scan ------------------------------
__global__ void __cluster_dims__(CLU, 1, 1) __launch_bounds__(256, 1)
scan_kernel(const int* __restrict__ text)
{
    __shared__ __align__(16) float Bf[2][CPC][C];
    __shared__ __align__(16) float part[4][CPC][CSL];
    __shared__ float red[CPC][CSL];
    __shared__ float smax[CLU][CPC];   // per-writer-rank slice maxima
    __shared__ float ls_s[CPC];
    __shared__ int toks[2][CPC];

    const int tid = threadIdx.x;
    const int rank = blockIdx.x & (CLU - 1);
    const int chain0 = (blockIdx.x >> 3) * CPC;
    const int c0 = rank * CSL;
    const int g = tid >> 6;
    const int cl = tid & 63;
    const int nn = tid >> 5;   // chain index for epilogue threads (tid<128)
    const int jj = tid & 31;

    unsigned long long P2[64];
#pragma unroll
    for (int k2 = 0; k2 < 64; ++k2) {
        float lo = g_P[(size_t)(g * 128 + 2 * k2) * C + c0 + cl];
        float hi = g_P[(size_t)(g * 128 + 2 * k2 + 1) * C + c0 + cl];
        P2[k2] = pk2(lo, hi);
    }

    if (tid < CPC) {
        toks[0][tid] = text[(chain0 + tid) * T + 0];
        toks[1][tid] = text[(chain0 + tid) * T + 1];
        ls_s[tid] = 0.f;
    }
    __syncthreads();

    // precomputed DSMEM addresses for epilogue lanes (tid<128)
    const int nnc = (tid < 128) ? nn : 0;
    unsigned dstD[2][CLU], dstS[CLU];
    {
        unsigned b0 = smem_u32(&Bf[0][0][0]) + (unsigned)((nnc * C + c0 + 2 * jj) * 4);
        unsigned b1 = smem_u32(&Bf[1][0][0]) + (unsigned)((nnc * C + c0 + 2 * jj) * 4);
        unsigned bs = smem_u32(&smax[0][0]) + (unsigned)((rank * CPC + nnc) * 4);
#pragma unroll
        for (int r = 0; r < CLU; ++r) {
            asm volatile("mapa.shared::cluster.u32 %0, %1, %2;"
                         : "=r"(dstD[0][r]) : "r"(b0), "r"(r));
            asm volatile("mapa.shared::cluster.u32 %0, %1, %2;"
                         : "=r"(dstD[1][r]) : "r"(b1), "r"(r));
            asm volatile("mapa.shared::cluster.u32 %0, %1, %2;"
                         : "=r"(dstS[r]) : "r"(bs), "r"(r));
        }
    }

    // alpha0 into Bf[0]
    for (int i = tid; i < CPC * C; i += 256) {
        int n = i >> 9, c = i & (C - 1);
        Bf[0][n][c] = g_startP[c] * g_emisT[(size_t)toks[0][n] * C + c];
    }
    __syncthreads();
    // publish slice max of alpha0 (feeds rescale at t=1)
    if (tid < 128) {
        float m = fmaxf(Bf[0][nn][c0 + 2 * jj], Bf[0][nn][c0 + 2 * jj + 1]);
        m = warpMax(m);
        if (jj == 0) {
#pragma unroll
            for (int r = 0; r < CLU; ++r)
                asm volatile("st.shared::cluster.b32 [%0], %1;"
                             :: "r"(dstS[r]), "f"(m) : "memory");
        }
    }
    asm volatile("barrier.cluster.arrive.aligned;" ::: "memory");

    for (int t = 1; t < T; ++t) {
        const int rb = (t - 1) & 1, wb = t & 1;
        const bool resc = ((t & 3) == 1);
        const bool pub  = ((t & 3) == 0);

        // prefetches overlap the in-flight barrier
        float ev0 = 0.f, ev1 = 0.f;
        if (tid < 128) {
            const float2 e2 = *(const float2*)(g_emisT +
                (size_t)toks[wb][nn] * C + c0 + 2 * jj);
            ev0 = e2.x; ev1 = e2.y;
        }
        if (tid >= 252 && t + 1 < T)
            toks[(t + 1) & 1][tid - 252] = text[(chain0 + tid - 252) * T + (t + 1)];

        asm volatile("barrier.cluster.wait.aligned;" ::: "memory");

        // rescale factor from published slice maxima (no scan, no extra sync)
        float inv = 1.f;
        if (resc && tid < 128) {
            float mx = smax[0][nn];
#pragma unroll
            for (int r = 1; r < CLU; ++r) mx = fmaxf(mx, smax[r][nn]);
            inv = 1.f / mx;
            if (jj == 0) ls_s[nn] += logf(mx);
        }

        // packed-FMA partial GEMV, 4 chains, this thread's 128-wide K-chunk
        unsigned long long a0 = 0ull, a1 = 0ull, a2 = 0ull, a3 = 0ull;
        {
            const ulonglong2* r0 = (const ulonglong2*)&Bf[rb][0][g * 128];
            const ulonglong2* r1 = (const ulonglong2*)&Bf[rb][1][g * 128];
            const ulonglong2* r2 = (const ulonglong2*)&Bf[rb][2][g * 128];
            const ulonglong2* r3 = (const ulonglong2*)&Bf[rb][3][g * 128];
#pragma unroll
            for (int k4 = 0; k4 < 32; ++k4) {
                const ulonglong2 v0 = r0[k4], v1 = r1[k4], v2 = r2[k4], v3 = r3[k4];
                const unsigned long long p0 = P2[2 * k4], p1 = P2[2 * k4 + 1];
                a0 = fma2(v0.x, p0, a0); a0 = fma2(v0.y, p1, a0);
                a1 = fma2(v1.x, p0, a1); a1 = fma2(v1.y, p1, a1);
                a2 = fma2(v2.x, p0, a2); a2 = fma2(v2.y, p1, a2);
                a3 = fma2(v3.x, p0, a3); a3 = fma2(v3.y, p1, a3);
            }
        }
        {
            float lo, hi;
            upk2(a0, lo, hi); part[g][0][cl] = lo + hi;
            upk2(a1, lo, hi); part[g][1][cl] = lo + hi;
            upk2(a2, lo, hi); part[g][2][cl] = lo + hi;
            upk2(a3, lo, hi); part[g][3][cl] = lo + hi;
        }
        __syncthreads();

        if (tid < 128) {
            const int cc = 2 * jj;
            float s0 = ((part[0][nn][cc] + part[1][nn][cc]) +
                        (part[2][nn][cc] + part[3][nn][cc])) * (ev0 * inv);
            float s1 = ((part[0][nn][cc + 1] + part[1][nn][cc + 1]) +
                        (part[2][nn][cc + 1] + part[3][nn][cc + 1])) * (ev1 * inv);
            // publish slice max for the rescale 1 step later
            if (pub) {
                float m = warpMax(fmaxf(s0, s1));
                if (jj == 0) {
#pragma unroll
                    for (int r = 0; r < CLU; ++r)
                        asm volatile("st.shared::cluster.b32 [%0], %1;"
                                     :: "r"(dstS[r]), "f"(m) : "memory");
                }
            }
            unsigned long long pk = pk2(s0, s1);
#pragma unroll
            for (int r = 0; r < CLU; ++r)
                asm volatile("st.shared::cluster.b64 [%0], %1;"
                             :: "r"(dstD[wb][r]), "l"(pk) : "memory");
        }
        asm volatile("barrier.cluster.arrive.aligned;" ::: "memory");
    }
    asm volatile("barrier.cluster.wait.aligned;" ::: "memory");

    // final: logZ[n] = ls[n] + log(sum_c Bf[(T-1)&1][n][c])
    {
        float sm = 0.f;
#pragma unroll
        for (int j = 0; j < 8; ++j) sm += Bf[(T - 1) & 1][g][cl + 64 * j];
        red[g][cl] = sm;
        __syncthreads();
        if (tid < 128) {
            float v = red[nn][jj] + red[nn][jj + 32];
            v = warpSum(v);
            if (jj == 0 && rank == 0)
                g_logZ[chain0 + nn] = ls_s[nn] + logf(v);
        }
    }
    // keep cluster alive until everyone finished reading Bf
    asm volatile("barrier.cluster.arrive.aligned;" ::: "memory");
    asm volatile("barrier.cluster.wait.aligned;" ::: "memory");
}

__global__ void final_sum_kernel(float* __restrict__ out)
{
    __shared__ float s[64];
    int tid = threadIdx.x;
    s[tid] = g_logZ[tid];
    __syncthreads();
#pragma unroll
    for (int o = 32; o > 0; o >>= 1) {
        if (tid < o) s[tid] += s[tid + o];
        __syncthreads();
    }
    if (tid == 0) out[0] = s[0];
}

extern "C" void kernel_launch(void* const* d_in, const int* in_sizes, int n_in,
                              void* d_out, int out_size)
{
    const int*   text  = (const int*)  d_in[0];
    const float* se    = (const float*)d_in[1];
    const float* sw    = (const float*)d_in[2];
    const float* sb    = (const float*)d_in[3];
    const float* srw   = (const float*)d_in[4];
    const float* srb   = (const float*)d_in[5];
    const float* state = (const float*)d_in[6];
    const float* nse   = (const float*)d_in[7];
    const float* pre   = (const float*)d_in[8];
    const float* trw   = (const float*)d_in[9];
    const float* trb   = (const float*)d_in[10];
    const float* term  = (const float*)d_in[11];
    float* out = (float*)d_out;

    start_kernel<<<1, 256>>>(se, sw, sb, srw, srb, nse);
    gemm_nt<<<dim3(C / GBN, C / GBM), 256>>>(state, nse, 0, C);
    p_softmax_kernel<<<C, 256>>>();
    term_mlp_kernel<<<C / TROWS, 256>>>(pre, trw, trb);
    gemm_nt<<<dim3(V / GBN, C / GBM), 256>>>(g_fe, term, 1, V);
    rowstats_kernel<<<C, 256>>>();
    norm_transpose_kernel<<<dim3(V / 32, C / 32), 256>>>();
    scan_kernel<<<(NB / CPC) * CLU, 256>>>(text);
    final_sum_kernel<<<1, 64>>>(out);
}

// round 8
// speedup vs baseline: 1.5375x; 1.0480x over previous
#include <cuda_runtime.h>
#include <cuda_bf16.h>
#include <cstdint>
#include <math.h>

#define H 256
#define C 512
#define V 32000
#define NB 64
#define T 512

#define CLU 8
#define CPC 4
#define CSL 64

__device__ float g_startP[C];
__device__ float g_P[C * C];
__device__ float g_fe[C * H];
__device__ float g_L[(size_t)C * V];
__device__ float g_rowoff[C];          // rowmax + log(sumexp): emis = exp(l - rowoff)
__device__ float g_logZ[NB];

__device__ __forceinline__ unsigned long long pk2(float lo, float hi) {
    unsigned long long r;
    asm("mov.b64 %0, {%1, %2};" : "=l"(r) : "f"(lo), "f"(hi));
    return r;
}
__device__ __forceinline__ void upk2(unsigned long long v, float& lo, float& hi) {
    asm("mov.b64 {%0, %1}, %2;" : "=f"(lo), "=f"(hi) : "l"(v));
}
__device__ __forceinline__ unsigned long long fma2(
    unsigned long long a, unsigned long long b, unsigned long long c) {
    unsigned long long d;
    asm("fma.rn.f32x2 %0, %1, %2, %3;" : "=l"(d) : "l"(a), "l"(b), "l"(c));
    return d;
}
__device__ __forceinline__ float warpMax(float v) {
#pragma unroll
    for (int o = 16; o > 0; o >>= 1) v = fmaxf(v, __shfl_xor_sync(0xffffffffu, v, o));
    return v;
}
__device__ __forceinline__ float warpSum(float v) {
#pragma unroll
    for (int o = 16; o > 0; o >>= 1) v += __shfl_xor_sync(0xffffffffu, v, o);
    return v;
}
__device__ __forceinline__ float blockMax256(float v, float* sred) {
    v = warpMax(v);
    int w = threadIdx.x >> 5, ln = threadIdx.x & 31;
    if (ln == 0) sred[w] = v;
    __syncthreads();
    if (w == 0) {
        float x = (ln < 8) ? sred[ln] : -3.4e38f;
        x = warpMax(x);
        if (ln == 0) sred[0] = x;
    }
    __syncthreads();
    float r = sred[0];
    __syncthreads();
    return r;
}
__device__ __forceinline__ float blockSum256(float v, float* sred) {
    v = warpSum(v);
    int w = threadIdx.x >> 5, ln = threadIdx.x & 31;
    if (ln == 0) sred[w] = v;
    __syncthreads();
    if (w == 0) {
        float x = (ln < 8) ? sred[ln] : 0.f;
        x = warpSum(x);
        if (ln == 0) sred[0] = x;
    }
    __syncthreads();
    float r = sred[0];
    __syncthreads();
    return r;
}
__device__ __forceinline__ unsigned smem_u32(const void* p) {
    return (unsigned)__cvta_generic_to_shared(p);
}

// --------------------- shared GEMM body (NT, 64x128x32, f32x2) -------------
#define GBM 64
#define GBN 128
#define GBK 32
__device__ void gemm_body(const float* __restrict__ A, const float* __restrict__ B,
                          float* __restrict__ Cout, int Ncols, int bm, int bn,
                          float* As /*[32][65]*/, float* Bs /*[32][132]*/)
{
    int tid = threadIdx.x;
    int tm = (tid >> 4) * 4;
    int tn = (tid & 15) * 8;
    unsigned long long acc2[4][4];
#pragma unroll
    for (int i = 0; i < 4; ++i)
#pragma unroll
        for (int j = 0; j < 4; ++j) acc2[i][j] = 0ull;

    for (int k0 = 0; k0 < H; k0 += GBK) {
#pragma unroll
        for (int q = 0; q < 2; ++q) {
            int i = tid + q * 256;
            int m = i >> 3, f = i & 7;
            float4 v = *(const float4*)(A + (size_t)(bm + m) * H + k0 + f * 4);
            As[(f * 4 + 0) * 65 + m] = v.x; As[(f * 4 + 1) * 65 + m] = v.y;
            As[(f * 4 + 2) * 65 + m] = v.z; As[(f * 4 + 3) * 65 + m] = v.w;
        }
#pragma unroll
        for (int q = 0; q < 4; ++q) {
            int i = tid + q * 256;
            int n = i >> 3, f = i & 7;
            float4 v = *(const float4*)(B + (size_t)(bn + n) * H + k0 + f * 4);
            Bs[(f * 4 + 0) * 132 + n] = v.x; Bs[(f * 4 + 1) * 132 + n] = v.y;
            Bs[(f * 4 + 2) * 132 + n] = v.z; Bs[(f * 4 + 3) * 132 + n] = v.w;
        }
        __syncthreads();
#pragma unroll
        for (int kk = 0; kk < GBK; ++kk) {
            unsigned long long ra2[4], rb2[4];
#pragma unroll
            for (int i = 0; i < 4; ++i) {
                float a = As[kk * 65 + tm + i];
                ra2[i] = pk2(a, a);
            }
            const unsigned long long* bp = (const unsigned long long*)&Bs[kk * 132 + tn];
#pragma unroll
            for (int j = 0; j < 4; ++j) rb2[j] = bp[j];
#pragma unroll
            for (int i = 0; i < 4; ++i)
#pragma unroll
                for (int j = 0; j < 4; ++j)
                    acc2[i][j] = fma2(ra2[i], rb2[j], acc2[i][j]);
        }
        __syncthreads();
    }
#pragma unroll
    for (int i = 0; i < 4; ++i) {
        float c[8];
#pragma unroll
        for (int j = 0; j < 4; ++j) upk2(acc2[i][j], c[2 * j], c[2 * j + 1]);
        *(float4*)(Cout + (size_t)(bm + tm + i) * Ncols + bn + tn) =
            make_float4(c[0], c[1], c[2], c[3]);
        *(float4*)(Cout + (size_t)(bm + tm + i) * Ncols + bn + tn + 4) =
            make_float4(c[4], c[5], c[6], c[7]);
    }
}

// ------------- k1: start MLP + terminal MLP + transition GEMM --------------
#define TROWS 4
__global__ __launch_bounds__(256) void fused_prep(
    const float* __restrict__ se, const float* __restrict__ sw,
    const float* __restrict__ sb, const float* __restrict__ srw,
    const float* __restrict__ srb, const float* __restrict__ nse,
    const float* __restrict__ pre, const float* __restrict__ trw,
    const float* __restrict__ trb, const float* __restrict__ state)
{
    __shared__ __align__(16) float pool[6304];
    int b = blockIdx.x;
    int tid = threadIdx.x;

    if (b == 0) {
        // ---- start vector ----
        float* x = pool;
        float* h = pool + 256;
        float* sred = pool + 512;
        x[tid] = se[tid];
        __syncthreads();
        {
            float a = sb[tid];
            for (int k0 = 0; k0 < H; k0 += 8) {
                float w[8];
#pragma unroll
                for (int u = 0; u < 8; ++u) w[u] = sw[(k0 + u) * H + tid];
#pragma unroll
                for (int u = 0; u < 8; ++u) a = fmaf(x[k0 + u], w[u], a);
            }
            __syncthreads();
            x[tid] = a;
            __syncthreads();
        }
        for (int l = 0; l < 2; ++l) {
            const float* w1 = srw + (size_t)(l * 2 + 0) * H * H;
            const float* b1 = srb + (l * 2 + 0) * H;
            const float* w2 = srw + (size_t)(l * 2 + 1) * H * H;
            const float* b2 = srb + (l * 2 + 1) * H;
            float a1 = b1[tid];
            for (int k0 = 0; k0 < H; k0 += 8) {
                float w[8];
#pragma unroll
                for (int u = 0; u < 8; ++u) w[u] = w1[(k0 + u) * H + tid];
#pragma unroll
                for (int u = 0; u < 8; ++u) a1 = fmaf(x[k0 + u], w[u], a1);
            }
            h[tid] = fmaxf(a1, 0.f);
            __syncthreads();
            float a2 = b2[tid];
            for (int k0 = 0; k0 < H; k0 += 8) {
                float w[8];
#pragma unroll
                for (int u = 0; u < 8; ++u) w[u] = w2[(k0 + u) * H + tid];
#pragma unroll
                for (int u = 0; u < 8; ++u) a2 = fmaf(h[k0 + u], w[u], a2);
            }
            __syncthreads();
            x[tid] += fmaxf(a2, 0.f);
            __syncthreads();
        }
        float l0 = 0.f, l1 = 0.f;
        const float4* r0 = (const float4*)(nse + (size_t)tid * H);
        const float4* r1 = (const float4*)(nse + (size_t)(tid + 256) * H);
        const float4* xv4 = (const float4*)x;
#pragma unroll 4
        for (int k4 = 0; k4 < H / 4; ++k4) {
            float4 xa = xv4[k4];
            float4 a = r0[k4], bb = r1[k4];
            l0 = fmaf(xa.x, a.x, l0); l0 = fmaf(xa.y, a.y, l0);
            l0 = fmaf(xa.z, a.z, l0); l0 = fmaf(xa.w, a.w, l0);
            l1 = fmaf(xa.x, bb.x, l1); l1 = fmaf(xa.y, bb.y, l1);
            l1 = fmaf(xa.z, bb.z, l1); l1 = fmaf(xa.w, bb.w, l1);
        }
        float m = blockMax256(fmaxf(l0, l1), sred);
        float e0 = expf(l0 - m), e1 = expf(l1 - m);
        float s = blockSum256(e0 + e1, sred);
        float inv = 1.f / s;
        g_startP[tid] = e0 * inv;
        g_startP[tid + 256] = e1 * inv;
    } else if (b <= 128) {
        // ---- terminal MLP (4 rows per block) ----
        float (*xs)[H] = (float(*)[H])pool;
        float (*hs)[H] = (float(*)[H])(pool + TROWS * H);
        int r0 = (b - 1) * TROWS;
        for (int i = tid; i < TROWS * H; i += 256)
            xs[i >> 8][i & 255] = pre[(size_t)(r0 + (i >> 8)) * H + (i & 255)];
        __syncthreads();
        for (int l = 0; l < 2; ++l) {
            const float* w1 = trw + (size_t)(l * 2 + 0) * H * H;
            const float* b1 = trb + (l * 2 + 0) * H;
            const float* w2 = trw + (size_t)(l * 2 + 1) * H * H;
            const float* b2 = trb + (l * 2 + 1) * H;
            float acc[TROWS];
#pragma unroll
            for (int r = 0; r < TROWS; ++r) acc[r] = b1[tid];
            for (int k0 = 0; k0 < H; k0 += 16) {
                float w[16];
#pragma unroll
                for (int u = 0; u < 16; ++u) w[u] = w1[(k0 + u) * H + tid];
#pragma unroll
                for (int u = 0; u < 16; ++u)
#pragma unroll
                    for (int r = 0; r < TROWS; ++r)
                        acc[r] = fmaf(xs[r][k0 + u], w[u], acc[r]);
            }
#pragma unroll
            for (int r = 0; r < TROWS; ++r) hs[r][tid] = fmaxf(acc[r], 0.f);
            __syncthreads();
#pragma unroll
            for (int r = 0; r < TROWS; ++r) acc[r] = b2[tid];
            for (int k0 = 0; k0 < H; k0 += 16) {
                float w[16];
#pragma unroll
                for (int u = 0; u < 16; ++u) w[u] = w2[(k0 + u) * H + tid];
#pragma unroll
                for (int u = 0; u < 16; ++u)
#pragma unroll
                    for (int r = 0; r < TROWS; ++r)
                        acc[r] = fmaf(hs[r][k0 + u], w[u], acc[r]);
            }
            __syncthreads();
#pragma unroll
            for (int r = 0; r < TROWS; ++r) xs[r][tid] += fmaxf(acc[r], 0.f);
            __syncthreads();
        }
        for (int i = tid; i < TROWS * H; i += 256)
            g_fe[(size_t)(r0 + (i >> 8)) * H + (i & 255)] = xs[i >> 8][i & 255];
    } else {
        // ---- transition logits GEMM: g_P[m][n] = state[m] . nse[n] ----
        int i = b - 129;                  // 0..31
        int bn = (i & 3) * GBN;
        int bm = (i >> 2) * GBM;
        gemm_body(state, nse, g_P, C, bm, bn, pool, pool + 2080);
    }
}

// ------------- k2: transition softmax + emission GEMM ----------------------
__global__ __launch_bounds__(256) void fused_sm_gemm(
    const float* __restrict__ term)
{
    __shared__ __align__(16) float pool[6304];
    int b = blockIdx.x;
    int tid = threadIdx.x;
    if (b < C) {
        // transition row softmax in place
        float* sred = pool;
        float* row = g_P + (size_t)b * C;
        float v0 = row[tid], v1 = row[tid + 256];
        float m = blockMax256(fmaxf(v0, v1), sred);
        float e0 = expf(v0 - m), e1 = expf(v1 - m);
        float s = blockSum256(e0 + e1, sred);
        float inv = 1.f / s;
        row[tid] = e0 * inv;
        row[tid + 256] = e1 * inv;
    } else {
        int i = b - C;                    // 0..1999
        int bn = (i % (V / GBN)) * GBN;
        int bm = (i / (V / GBN)) * GBM;
        gemm_body(g_fe, term, g_L, V, bm, bn, pool, pool + 2080);
    }
}

// ------------- k3: emission row offsets (rowmax + log sumexp) ---------------
__global__ __launch_bounds__(256) void rowstats_kernel()
{
    __shared__ float sred[32];
    int c = blockIdx.x;
    int tid = threadIdx.x;
    const float4* row = (const float4*)(g_L + (size_t)c * V);
    float mx = -3.4e38f;
    for (int i = tid; i < V / 4; i += 256) {
        float4 v = row[i];
        mx = fmaxf(mx, fmaxf(fmaxf(v.x, v.y), fmaxf(v.z, v.w)));
    }
    float m = blockMax256(mx, sred);
    float s = 0.f;
    for (int i = tid; i < V / 4; i += 256) {
        float4 v = row[i];
        s += expf(v.x - m) + expf(v.y - m) + expf(v.z - m) + expf(v.w - m);
    }
    float tot = blockSum256(s, sred);
    if (tid == 0) g_rowoff[c] = m + logf(tot);
}

// ------------------------------ k4: HMM scan -------------------------------
__global__ void __cluster_dims__(CLU, 1, 1) __launch_bounds__(256, 1)
scan_kernel(const int* __restrict__ text)
{
    __shared__ __align__(16) float Bf[2][CPC][C];
    __shared__ __align__(16) float part[4][CPC][CSL];
    __shared__ float red[CPC][CSL];
    __shared__ float inv_s[CPC];
    __shared__ float ls_s[CPC];
    __shared__ int toks[2][CPC];

    const int tid = threadIdx.x;
    const int rank = blockIdx.x & (CLU - 1);
    const int chain0 = (blockIdx.x >> 3) * CPC;
    const int c0 = rank * CSL;
    const int g = tid >> 6;
    const int cl = tid & 63;
    const int nn = tid >> 5;       // epilogue chain idx (tid<128)
    const int jj = tid & 31;

    // P slice packed along k (register resident)
    unsigned long long P2[64];
#pragma unroll
    for (int k2 = 0; k2 < 64; ++k2) {
        float lo = g_P[(size_t)(g * 128 + 2 * k2) * C + c0 + cl];
        float hi = g_P[(size_t)(g * 128 + 2 * k2 + 1) * C + c0 + cl];
        P2[k2] = pk2(lo, hi);
    }

    if (tid < CPC) {
        toks[0][tid] = text[(chain0 + tid) * T + 0];
        toks[1][tid] = text[(chain0 + tid) * T + 1];
        ls_s[tid] = 0.f;
        inv_s[tid] = 1.f;
    }
    __syncthreads();

    // emission column state for epilogue threads (fixed 2 columns each)
    const float* pL0 = g_L + (size_t)(c0 + 2 * jj) * V;
    const float* pL1 = pL0 + V;
    const float off0 = g_rowoff[c0 + 2 * jj];
    const float off1 = g_rowoff[c0 + 2 * jj + 1];

    // precomputed remote store addresses (epilogue lanes)
    const int nnc = (tid < 128) ? nn : 0;
    unsigned dstD[2][CLU];
    {
        unsigned b0 = smem_u32(&Bf[0][0][0]) + (unsigned)((nnc * C + c0 + 2 * jj) * 4);
        unsigned b1 = smem_u32(&Bf[1][0][0]) + (unsigned)((nnc * C + c0 + 2 * jj) * 4);
#pragma unroll
        for (int r = 0; r < CLU; ++r) {
            asm volatile("mapa.shared::cluster.u32 %0, %1, %2;"
                         : "=r"(dstD[0][r]) : "r"(b0), "r"(r));
            asm volatile("mapa.shared::cluster.u32 %0, %1, %2;"
                         : "=r"(dstD[1][r]) : "r"(b1), "r"(r));
        }
    }

    // alpha0 into Bf[0]: full replicated copy computed locally from g_L
    for (int i = tid; i < CPC * C; i += 256) {
        int n = i >> 9, c = i & (C - 1);
        float lv = g_L[(size_t)c * V + toks[0][n]];
        Bf[0][n][c] = g_startP[c] * __expf(lv - g_rowoff[c]);
    }
    __syncthreads();

    for (int t = 1; t < T; ++t) {
        const int rb = (t - 1) & 1, wb = t & 1;
        const bool resc = ((t & 3) == 1);

        // emission prefetch: direct gather from g_L with fused exp
        float ev0 = 0.f, ev1 = 0.f;
        if (tid < 128) {
            const int tok = toks[wb][nn];
            float lv0 = pL0[tok];
            float lv1 = pL1[tok];
            ev0 = __expf(lv0 - off0);
            ev1 = __expf(lv1 - off1);
        }
        if (tid >= 252 && t + 1 < T)
            toks[(t + 1) & 1][tid - 252] = text[(chain0 + tid - 252) * T + (t + 1)];

        // deferred rescale bookkeeping every 4 steps
        if (resc) {
            float mx = 0.f;
#pragma unroll
            for (int j = 0; j < 8; ++j) mx = fmaxf(mx, Bf[rb][g][cl + 64 * j]);
            red[g][cl] = mx;
            __syncthreads();
            if (tid < 128) {
                float v = fmaxf(red[nn][jj], red[nn][jj + 32]);
                v = warpMax(v);
                if (jj == 0) { inv_s[nn] = 1.f / v; ls_s[nn] += logf(v); }
            }
            __syncthreads();
        }

        // packed-FMA partial GEMV, 4 chains, this thread's 128-wide K-chunk
        unsigned long long a0 = 0ull, a1 = 0ull, a2 = 0ull, a3 = 0ull;
        {
            const ulonglong2* r0 = (const ulonglong2*)&Bf[rb][0][g * 128];
            const ulonglong2* r1 = (const ulonglong2*)&Bf[rb][1][g * 128];
            const ulonglong2* r2 = (const ulonglong2*)&Bf[rb][2][g * 128];
            const ulonglong2* r3 = (const ulonglong2*)&Bf[rb][3][g * 128];
#pragma unroll
            for (int k4 = 0; k4 < 32; ++k4) {
                const ulonglong2 v0 = r0[k4], v1 = r1[k4], v2 = r2[k4], v3 = r3[k4];
                const unsigned long long p0 = P2[2 * k4], p1 = P2[2 * k4 + 1];
                a0 = fma2(v0.x, p0, a0); a0 = fma2(v0.y, p1, a0);
                a1 = fma2(v1.x, p0, a1); a1 = fma2(v1.y, p1, a1);
                a2 = fma2(v2.x, p0, a2); a2 = fma2(v2.y, p1, a2);
                a3 = fma2(v3.x, p0, a3); a3 = fma2(v3.y, p1, a3);
            }
        }
        {
            float lo, hi;
            upk2(a0, lo, hi); part[g][0][cl] = lo + hi;
            upk2(a1, lo, hi); part[g][1][cl] = lo + hi;
            upk2(a2, lo, hi); part[g][2][cl] = lo + hi;
            upk2(a3, lo, hi); part[g][3][cl] = lo + hi;
        }
        __syncthreads();

        if (tid < 128) {
            const int cc = 2 * jj;
            const float inv = resc ? inv_s[nn] : 1.f;
            float s0 = ((part[0][nn][cc] + part[1][nn][cc]) +
                        (part[2][nn][cc] + part[3][nn][cc])) * (ev0 * inv);
            float s1 = ((part[0][nn][cc + 1] + part[1][nn][cc + 1]) +
                        (part[2][nn][cc + 1] + part[3][nn][cc + 1])) * (ev1 * inv);
            unsigned long long pk = pk2(s0, s1);
#pragma unroll
            for (int r = 0; r < CLU; ++r)
                asm volatile("st.shared::cluster.b64 [%0], %1;"
                             :: "r"(dstD[wb][r]), "l"(pk) : "memory");
        }
        asm volatile("barrier.cluster.arrive.aligned;" ::: "memory");
        asm volatile("barrier.cluster.wait.aligned;" ::: "memory");
    }

    // final: logZ[n] = ls[n] + log(sum_c Bf[(T-1)&1][n][c])
    {
        float sm = 0.f;
#pragma unroll
        for (int j = 0; j < 8; ++j) sm += Bf[(T - 1) & 1][g][cl + 64 * j];
        red[g][cl] = sm;
        __syncthreads();
        if (tid < 128) {
            float v = red[nn][jj] + red[nn][jj + 32];
            v = warpSum(v);
            if (jj == 0 && rank == 0)
                g_logZ[chain0 + nn] = ls_s[nn] + logf(v);
        }
    }
}

__global__ void final_sum_kernel(float* __restrict__ out)
{
    __shared__ float s[64];
    int tid = threadIdx.x;
    s[tid] = g_logZ[tid];
    __syncthreads();
#pragma unroll
    for (int o = 32; o > 0; o >>= 1) {
        if (tid < o) s[tid] += s[tid + o];
        __syncthreads();
    }
    if (tid == 0) out[0] = s[0];
}

extern "C" void kernel_launch(void* const* d_in, const int* in_sizes, int n_in,
                              void* d_out, int out_size)
{
    const int*   text  = (const int*)  d_in[0];
    const float* se    = (const float*)d_in[1];
    const float* sw    = (const float*)d_in[2];
    const float* sb    = (const float*)d_in[3];
    const float* srw   = (const float*)d_in[4];
    const float* srb   = (const float*)d_in[5];
    const float* state = (const float*)d_in[6];
    const float* nse   = (const float*)d_in[7];
    const float* pre   = (const float*)d_in[8];
    const float* trw   = (const float*)d_in[9];
    const float* trb   = (const float*)d_in[10];
    const float* term  = (const float*)d_in[11];
    float* out = (float*)d_out;

    fused_prep<<<1 + 128 + 32, 256>>>(se, sw, sb, srw, srb, nse,
                                      pre, trw, trb, state);
    fused_sm_gemm<<<C + (V / GBN) * (C / GBM), 256>>>(term);
    rowstats_kernel<<<C, 256>>>();
    scan_kernel<<<(NB / CPC) * CLU, 256>>>(text);
    final_sum_kernel<<<1, 64>>>(out);
}

// round 9
// speedup vs baseline: 1.6199x; 1.0536x over previous
#include <cuda_runtime.h>
#include <cuda_bf16.h>
#include <cstdint>
#include <math.h>

#define H 256
#define C 512
#define V 32000
#define NB 64
#define T 512

#define CLU 8
#define CPC 4
#define CSL 64

__device__ float g_startP[C];
__device__ float g_P[C * C];
__device__ float g_fe[C * H];
__device__ float g_L[(size_t)C * V];
__device__ float g_rowoff[C];          // rowmax + log(sumexp): emis = exp(l - rowoff)
__device__ float g_logZ[NB];

__device__ __forceinline__ unsigned long long pk2(float lo, float hi) {
    unsigned long long r;
    asm("mov.b64 %0, {%1, %2};" : "=l"(r) : "f"(lo), "f"(hi));
    return r;
}
__device__ __forceinline__ void upk2(unsigned long long v, float& lo, float& hi) {
    asm("mov.b64 {%0, %1}, %2;" : "=f"(lo), "=f"(hi) : "l"(v));
}
__device__ __forceinline__ unsigned long long fma2(
    unsigned long long a, unsigned long long b, unsigned long long c) {
    unsigned long long d;
    asm("fma.rn.f32x2 %0, %1, %2, %3;" : "=l"(d) : "l"(a), "l"(b), "l"(c));
    return d;
}
__device__ __forceinline__ float warpMax(float v) {
#pragma unroll
    for (int o = 16; o > 0; o >>= 1) v = fmaxf(v, __shfl_xor_sync(0xffffffffu, v, o));
    return v;
}
__device__ __forceinline__ float warpSum(float v) {
#pragma unroll
    for (int o = 16; o > 0; o >>= 1) v += __shfl_xor_sync(0xffffffffu, v, o);
    return v;
}
__device__ __forceinline__ float blockMax256(float v, float* sred) {
    v = warpMax(v);
    int w = threadIdx.x >> 5, ln = threadIdx.x & 31;
    if (ln == 0) sred[w] = v;
    __syncthreads();
    if (w == 0) {
        float x = (ln < 8) ? sred[ln] : -3.4e38f;
        x = warpMax(x);
        if (ln == 0) sred[0] = x;
    }
    __syncthreads();
    float r = sred[0];
    __syncthreads();
    return r;
}
__device__ __forceinline__ float blockSum256(float v, float* sred) {
    v = warpSum(v);
    int w = threadIdx.x >> 5, ln = threadIdx.x & 31;
    if (ln == 0) sred[w] = v;
    __syncthreads();
    if (w == 0) {
        float x = (ln < 8) ? sred[ln] : 0.f;
        x = warpSum(x);
        if (ln == 0) sred[0] = x;
    }
    __syncthreads();
    float r = sred[0];
    __syncthreads();
    return r;
}
__device__ __forceinline__ unsigned smem_u32(const void* p) {
    return (unsigned)__cvta_generic_to_shared(p);
}

// --------------------- shared GEMM body (NT, 64x128x32, f32x2) -------------
#define GBM 64
#define GBN 128
#define GBK 32
__device__ void gemm_body(const float* __restrict__ A, const float* __restrict__ B,
                          float* __restrict__ Cout, int Ncols, int bm, int bn,
                          float* As /*[32][65]*/, float* Bs /*[32][132]*/)
{
    int tid = threadIdx.x;
    int tm = (tid >> 4) * 4;
    int tn = (tid & 15) * 8;
    unsigned long long acc2[4][4];
#pragma unroll
    for (int i = 0; i < 4; ++i)
#pragma unroll
        for (int j = 0; j < 4; ++j) acc2[i][j] = 0ull;

    for (int k0 = 0; k0 < H; k0 += GBK) {
#pragma unroll
        for (int q = 0; q < 2; ++q) {
            int i = tid + q * 256;
            int m = i >> 3, f = i & 7;
            float4 v = *(const float4*)(A + (size_t)(bm + m) * H + k0 + f * 4);
            As[(f * 4 + 0) * 65 + m] = v.x; As[(f * 4 + 1) * 65 + m] = v.y;
            As[(f * 4 + 2) * 65 + m] = v.z; As[(f * 4 + 3) * 65 + m] = v.w;
        }
#pragma unroll
        for (int q = 0; q < 4; ++q) {
            int i = tid + q * 256;
            int n = i >> 3, f = i & 7;
            float4 v = *(const float4*)(B + (size_t)(bn + n) * H + k0 + f * 4);
            Bs[(f * 4 + 0) * 132 + n] = v.x; Bs[(f * 4 + 1) * 132 + n] = v.y;
            Bs[(f * 4 + 2) * 132 + n] = v.z; Bs[(f * 4 + 3) * 132 + n] = v.w;
        }
        __syncthreads();
#pragma unroll
        for (int kk = 0; kk < GBK; ++kk) {
            unsigned long long ra2[4], rb2[4];
#pragma unroll
            for (int i = 0; i < 4; ++i) {
                float a = As[kk * 65 + tm + i];
                ra2[i] = pk2(a, a);
            }
            const unsigned long long* bp = (const unsigned long long*)&Bs[kk * 132 + tn];
#pragma unroll
            for (int j = 0; j < 4; ++j) rb2[j] = bp[j];
#pragma unroll
            for (int i = 0; i < 4; ++i)
#pragma unroll
                for (int j = 0; j < 4; ++j)
                    acc2[i][j] = fma2(ra2[i], rb2[j], acc2[i][j]);
        }
        __syncthreads();
    }
#pragma unroll
    for (int i = 0; i < 4; ++i) {
        float c[8];
#pragma unroll
        for (int j = 0; j < 4; ++j) upk2(acc2[i][j], c[2 * j], c[2 * j + 1]);
        *(float4*)(Cout + (size_t)(bm + tm + i) * Ncols + bn + tn) =
            make_float4(c[0], c[1], c[2], c[3]);
        *(float4*)(Cout + (size_t)(bm + tm + i) * Ncols + bn + tn + 4) =
            make_float4(c[4], c[5], c[6], c[7]);
    }
}

// ------------- k1: start MLP + terminal MLP + transition GEMM --------------
#define TROWS 4
__global__ __launch_bounds__(256) void fused_prep(
    const float* __restrict__ se, const float* __restrict__ sw,
    const float* __restrict__ sb, const float* __restrict__ srw,
    const float* __restrict__ srb, const float* __restrict__ nse,
    const float* __restrict__ pre, const float* __restrict__ trw,
    const float* __restrict__ trb, const float* __restrict__ state)
{
    __shared__ __align__(16) float pool[6304];
    int b = blockIdx.x;
    int tid = threadIdx.x;

    if (b == 0) {
        float* x = pool;
        float* h = pool + 256;
        float* sred = pool + 512;
        x[tid] = se[tid];
        __syncthreads();
        {
            float a = sb[tid];
            for (int k0 = 0; k0 < H; k0 += 8) {
                float w[8];
#pragma unroll
                for (int u = 0; u < 8; ++u) w[u] = sw[(k0 + u) * H + tid];
#pragma unroll
                for (int u = 0; u < 8; ++u) a = fmaf(x[k0 + u], w[u], a);
            }
            __syncthreads();
            x[tid] = a;
            __syncthreads();
        }
        for (int l = 0; l < 2; ++l) {
            const float* w1 = srw + (size_t)(l * 2 + 0) * H * H;
            const float* b1 = srb + (l * 2 + 0) * H;
            const float* w2 = srw + (size_t)(l * 2 + 1) * H * H;
            const float* b2 = srb + (l * 2 + 1) * H;
            float a1 = b1[tid];
            for (int k0 = 0; k0 < H; k0 += 8) {
                float w[8];
#pragma unroll
                for (int u = 0; u < 8; ++u) w[u] = w1[(k0 + u) * H + tid];
#pragma unroll
                for (int u = 0; u < 8; ++u) a1 = fmaf(x[k0 + u], w[u], a1);
            }
            h[tid] = fmaxf(a1, 0.f);
            __syncthreads();
            float a2 = b2[tid];
            for (int k0 = 0; k0 < H; k0 += 8) {
                float w[8];
#pragma unroll
                for (int u = 0; u < 8; ++u) w[u] = w2[(k0 + u) * H + tid];
#pragma unroll
                for (int u = 0; u < 8; ++u) a2 = fmaf(h[k0 + u], w[u], a2);
            }
            __syncthreads();
            x[tid] += fmaxf(a2, 0.f);
            __syncthreads();
        }
        float l0 = 0.f, l1 = 0.f;
        const float4* r0 = (const float4*)(nse + (size_t)tid * H);
        const float4* r1 = (const float4*)(nse + (size_t)(tid + 256) * H);
        const float4* xv4 = (const float4*)x;
#pragma unroll 4
        for (int k4 = 0; k4 < H / 4; ++k4) {
            float4 xa = xv4[k4];
            float4 a = r0[k4], bb = r1[k4];
            l0 = fmaf(xa.x, a.x, l0); l0 = fmaf(xa.y, a.y, l0);
            l0 = fmaf(xa.z, a.z, l0); l0 = fmaf(xa.w, a.w, l0);
            l1 = fmaf(xa.x, bb.x, l1); l1 = fmaf(xa.y, bb.y, l1);
            l1 = fmaf(xa.z, bb.z, l1); l1 = fmaf(xa.w, bb.w, l1);
        }
        float m = blockMax256(fmaxf(l0, l1), sred);
        float e0 = expf(l0 - m), e1 = expf(l1 - m);
        float s = blockSum256(e0 + e1, sred);
        float inv = 1.f / s;
        g_startP[tid] = e0 * inv;
        g_startP[tid + 256] = e1 * inv;
    } else if (b <= 128) {
        float (*xs)[H] = (float(*)[H])pool;
        float (*hs)[H] = (float(*)[H])(pool + TROWS * H);
        int r0 = (b - 1) * TROWS;
        for (int i = tid; i < TROWS * H; i += 256)
            xs[i >> 8][i & 255] = pre[(size_t)(r0 + (i >> 8)) * H + (i & 255)];
        __syncthreads();
        for (int l = 0; l < 2; ++l) {
            const float* w1 = trw + (size_t)(l * 2 + 0) * H * H;
            const float* b1 = trb + (l * 2 + 0) * H;
            const float* w2 = trw + (size_t)(l * 2 + 1) * H * H;
            const float* b2 = trb + (l * 2 + 1) * H;
            float acc[TROWS];
#pragma unroll
            for (int r = 0; r < TROWS; ++r) acc[r] = b1[tid];
            for (int k0 = 0; k0 < H; k0 += 16) {
                float w[16];
#pragma unroll
                for (int u = 0; u < 16; ++u) w[u] = w1[(k0 + u) * H + tid];
#pragma unroll
                for (int u = 0; u < 16; ++u)
#pragma unroll
                    for (int r = 0; r < TROWS; ++r)
                        acc[r] = fmaf(xs[r][k0 + u], w[u], acc[r]);
            }
#pragma unroll
            for (int r = 0; r < TROWS; ++r) hs[r][tid] = fmaxf(acc[r], 0.f);
            __syncthreads();
#pragma unroll
            for (int r = 0; r < TROWS; ++r) acc[r] = b2[tid];
            for (int k0 = 0; k0 < H; k0 += 16) {
                float w[16];
#pragma unroll
                for (int u = 0; u < 16; ++u) w[u] = w2[(k0 + u) * H + tid];
#pragma unroll
                for (int u = 0; u < 16; ++u)
#pragma unroll
                    for (int r = 0; r < TROWS; ++r)
                        acc[r] = fmaf(hs[r][k0 + u], w[u], acc[r]);
            }
            __syncthreads();
#pragma unroll
            for (int r = 0; r < TROWS; ++r) xs[r][tid] += fmaxf(acc[r], 0.f);
            __syncthreads();
        }
        for (int i = tid; i < TROWS * H; i += 256)
            g_fe[(size_t)(r0 + (i >> 8)) * H + (i & 255)] = xs[i >> 8][i & 255];
    } else {
        int i = b - 129;
        int bn = (i & 3) * GBN;
        int bm = (i >> 2) * GBM;
        gemm_body(state, nse, g_P, C, bm, bn, pool, pool + 2080);
    }
}

// ------------- k2: transition softmax + emission GEMM ----------------------
__global__ __launch_bounds__(256) void fused_sm_gemm(
    const float* __restrict__ term)
{
    __shared__ __align__(16) float pool[6304];
    int b = blockIdx.x;
    int tid = threadIdx.x;
    if (b < C) {
        float* sred = pool;
        float* row = g_P + (size_t)b * C;
        float v0 = row[tid], v1 = row[tid + 256];
        float m = blockMax256(fmaxf(v0, v1), sred);
        float e0 = expf(v0 - m), e1 = expf(v1 - m);
        float s = blockSum256(e0 + e1, sred);
        float inv = 1.f / s;
        row[tid] = e0 * inv;
        row[tid + 256] = e1 * inv;
    } else {
        int i = b - C;
        int bn = (i % (V / GBN)) * GBN;
        int bm = (i / (V / GBN)) * GBM;
        gemm_body(g_fe, term, g_L, V, bm, bn, pool, pool + 2080);
    }
}

// ------------- k3: emission row offsets (rowmax + log sumexp) ---------------
__global__ __launch_bounds__(256) void rowstats_kernel()
{
    __shared__ float sred[32];
    int c = blockIdx.x;
    int tid = threadIdx.x;
    const float4* row = (const float4*)(g_L + (size_t)c * V);
    float mx = -3.4e38f;
    for (int i = tid; i < V / 4; i += 256) {
        float4 v = row[i];
        mx = fmaxf(mx, fmaxf(fmaxf(v.x, v.y), fmaxf(v.z, v.w)));
    }
    float m = blockMax256(mx, sred);
    float s = 0.f;
    for (int i = tid; i < V / 4; i += 256) {
        float4 v = row[i];
        s += expf(v.x - m) + expf(v.y - m) + expf(v.z - m) + expf(v.w - m);
    }
    float tot = blockSum256(s, sred);
    if (tid == 0) g_rowoff[c] = m + logf(tot);
}

// ------------------------------ k4: HMM scan -------------------------------
// Thread tiling: cq = tid&15 (4 output cols each), kg = tid>>4 (32-deep K chunk).
// LDS per thread per step: 32 LDS.128 (was 128). FMA2: 256 (unchanged).
__global__ void __cluster_dims__(CLU, 1, 1) __launch_bounds__(256, 1)
scan_kernel(const int* __restrict__ text)
{
    __shared__ __align__(16) float Bf[2][CPC][C];        // 16 KB
    __shared__ __align__(16) float part[16][CPC][CSL];   // 16 KB
    __shared__ float red[CPC][CSL];
    __shared__ float inv_s[CPC];
    __shared__ float ls_s[CPC];
    __shared__ int toks[2][CPC];

    const int tid = threadIdx.x;
    const int rank = blockIdx.x & (CLU - 1);
    const int chain0 = (blockIdx.x >> 3) * CPC;
    const int c0 = rank * CSL;
    const int cq = tid & 15;       // producer: col quad
    const int kg = tid >> 4;       // producer: k-group (32 wide)
    const int ch = tid >> 6;       // epilogue: chain
    const int col = tid & 63;      // epilogue: column
    const int jj = tid & 31;

    // P2[k2*4+j] = {P[32kg+2k2][c0+4cq+j], P[32kg+2k2+1][c0+4cq+j]}
    unsigned long long P2[64];
#pragma unroll
    for (int k2 = 0; k2 < 16; ++k2) {
#pragma unroll
        for (int j = 0; j < 4; ++j) {
            int c = c0 + 4 * cq + j;
            float lo = g_P[(size_t)(32 * kg + 2 * k2) * C + c];
            float hi = g_P[(size_t)(32 * kg + 2 * k2 + 1) * C + c];
            P2[k2 * 4 + j] = pk2(lo, hi);
        }
    }

    if (tid < CPC) {
        toks[0][tid] = text[(chain0 + tid) * T + 0];
        toks[1][tid] = text[(chain0 + tid) * T + 1];
        ls_s[tid] = 0.f;
        inv_s[tid] = 1.f;
    }
    __syncthreads();

    // per-thread emission column state (1 column each)
    const float* pLc = g_L + (size_t)(c0 + col) * V;
    const float offc = g_rowoff[c0 + col];

    // precomputed remote store addresses (even-lane threads store col,col+1)
    unsigned dstD[2][CLU];
    {
        unsigned b0 = smem_u32(&Bf[0][0][0]) + (unsigned)((ch * C + c0 + col) * 4);
        unsigned b1 = smem_u32(&Bf[1][0][0]) + (unsigned)((ch * C + c0 + col) * 4);
#pragma unroll
        for (int r = 0; r < CLU; ++r) {
            asm volatile("mapa.shared::cluster.u32 %0, %1, %2;"
                         : "=r"(dstD[0][r]) : "r"(b0), "r"(r));
            asm volatile("mapa.shared::cluster.u32 %0, %1, %2;"
                         : "=r"(dstD[1][r]) : "r"(b1), "r"(r));
        }
    }

    // alpha0 into Bf[0]
    for (int i = tid; i < CPC * C; i += 256) {
        int n = i >> 9, c = i & (C - 1);
        float lv = g_L[(size_t)c * V + toks[0][n]];
        Bf[0][n][c] = g_startP[c] * __expf(lv - g_rowoff[c]);
    }
    __syncthreads();

    for (int t = 1; t < T; ++t) {
        const int rb = (t - 1) & 1, wb = t & 1;
        const bool resc = ((t & 3) == 1);

        // emission prefetch (1 column per thread)
        float ev;
        {
            const int tok = toks[wb][ch];
            ev = __expf(pLc[tok] - offc);
        }
        if (tid >= 252 && t + 1 < T)
            toks[(t + 1) & 1][tid - 252] = text[(chain0 + tid - 252) * T + (t + 1)];

        // deferred rescale bookkeeping every 4 steps
        if (resc) {
            float mx = 0.f;
#pragma unroll
            for (int j = 0; j < 8; ++j) mx = fmaxf(mx, Bf[rb][ch][col + 64 * j]);
            red[ch][col] = mx;
            __syncthreads();
            if (tid < 128) {
                int n2 = tid >> 5;
                float v = fmaxf(red[n2][jj], red[n2][jj + 32]);
                v = warpMax(v);
                if (jj == 0) { inv_s[n2] = 1.f / v; ls_s[n2] += logf(v); }
            }
            __syncthreads();
        }

        // GEMV: 4 cols x 4 chains x 32 k per thread, packed over k
        unsigned long long acc[16];
#pragma unroll
        for (int i = 0; i < 16; ++i) acc[i] = 0ull;
#pragma unroll
        for (int c4 = 0; c4 < CPC; ++c4) {
            unsigned long long av[16];
            const ulonglong2* ap = (const ulonglong2*)&Bf[rb][c4][kg * 32];
#pragma unroll
            for (int u = 0; u < 8; ++u) {
                ulonglong2 tv = ap[u];
                av[2 * u] = tv.x; av[2 * u + 1] = tv.y;
            }
#pragma unroll
            for (int k2 = 0; k2 < 16; ++k2) {
#pragma unroll
                for (int j = 0; j < 4; ++j)
                    acc[c4 * 4 + j] = fma2(av[k2], P2[k2 * 4 + j], acc[c4 * 4 + j]);
            }
        }
        // fold packed lanes, store partials: part[kg][chain][4cq..4cq+3]
#pragma unroll
        for (int c4 = 0; c4 < CPC; ++c4) {
            float4 v;
            float lo, hi;
            upk2(acc[c4 * 4 + 0], lo, hi); v.x = lo + hi;
            upk2(acc[c4 * 4 + 1], lo, hi); v.y = lo + hi;
            upk2(acc[c4 * 4 + 2], lo, hi); v.z = lo + hi;
            upk2(acc[c4 * 4 + 3], lo, hi); v.w = lo + hi;
            *(float4*)&part[kg][c4][4 * cq] = v;
        }
        __syncthreads();

        // epilogue: every thread owns one output (ch, col)
        {
            float p[16];
#pragma unroll
            for (int q = 0; q < 16; ++q) p[q] = part[q][ch][col];
            float s = (((p[0] + p[1]) + (p[2] + p[3])) +
                       ((p[4] + p[5]) + (p[6] + p[7]))) +
                      (((p[8] + p[9]) + (p[10] + p[11])) +
                       ((p[12] + p[13]) + (p[14] + p[15])));
            const float inv = resc ? inv_s[ch] : 1.f;
            float val = s * (ev * inv);
            float other = __shfl_down_sync(0xffffffffu, val, 1);
            if (!(tid & 1)) {
                unsigned long long pk = pk2(val, other);
#pragma unroll
                for (int r = 0; r < CLU; ++r)
                    asm volatile("st.shared::cluster.b64 [%0], %1;"
                                 :: "r"(dstD[wb][r]), "l"(pk) : "memory");
            }
        }
        asm volatile("barrier.cluster.arrive.aligned;" ::: "memory");
        asm volatile("barrier.cluster.wait.aligned;" ::: "memory");
    }

    // final: logZ[n] = ls[n] + log(sum_c Bf[(T-1)&1][n][c])
    {
        float sm = 0.f;
#pragma unroll
        for (int j = 0; j < 8; ++j) sm += Bf[(T - 1) & 1][ch][col + 64 * j];
        red[ch][col] = sm;
        __syncthreads();
        if (tid < 128) {
            int n2 = tid >> 5;
            float v = red[n2][jj] + red[n2][jj + 32];
            v = warpSum(v);
            if (jj == 0 && rank == 0)
                g_logZ[chain0 + n2] = ls_s[n2] + logf(v);
        }
    }
}

__global__ void final_sum_kernel(float* __restrict__ out)
{
    __shared__ float s[64];
    int tid = threadIdx.x;
    s[tid] = g_logZ[tid];
    __syncthreads();
#pragma unroll
    for (int o = 32; o > 0; o >>= 1) {
        if (tid < o) s[tid] += s[tid + o];
        __syncthreads();
    }
    if (tid == 0) out[0] = s[0];
}

extern "C" void kernel_launch(void* const* d_in, const int* in_sizes, int n_in,
                              void* d_out, int out_size)
{
    const int*   text  = (const int*)  d_in[0];
    const float* se    = (const float*)d_in[1];
    const float* sw    = (const float*)d_in[2];
    const float* sb    = (const float*)d_in[3];
    const float* srw   = (const float*)d_in[4];
    const float* srb   = (const float*)d_in[5];
    const float* state = (const float*)d_in[6];
    const float* nse   = (const float*)d_in[7];
    const float* pre   = (const float*)d_in[8];
    const float* trw   = (const float*)d_in[9];
    const float* trb   = (const float*)d_in[10];
    const float* term  = (const float*)d_in[11];
    float* out = (float*)d_out;

    fused_prep<<<1 + 128 + 32, 256>>>(se, sw, sb, srw, srb, nse,
                                      pre, trw, trb, state);
    fused_sm_gemm<<<C + (V / GBN) * (C / GBM), 256>>>(term);
    rowstats_kernel<<<C, 256>>>();
    scan_kernel<<<(NB / CPC) * CLU, 256>>>(text);
    final_sum_kernel<<<1, 64>>>(out);
}

// round 10
// speedup vs baseline: 1.6664x; 1.0287x over previous
#include <cuda_runtime.h>
#include <cuda_bf16.h>
#include <cstdint>
#include <math.h>

#define H 256
#define C 512
#define V 32000
#define NB 64
#define T 512

#define CLU 8
#define CPC 4
#define CSL 64

__device__ float g_startP[C];
__device__ float g_P[C * C];
__device__ float g_fe[C * H];
__device__ float g_L[(size_t)C * V];
__device__ float g_rowoff[C];          // rowmax + log(sumexp): emis = exp(l - rowoff)
__device__ float g_logZ[NB];

__device__ __forceinline__ unsigned long long pk2(float lo, float hi) {
    unsigned long long r;
    asm("mov.b64 %0, {%1, %2};" : "=l"(r) : "f"(lo), "f"(hi));
    return r;
}
__device__ __forceinline__ void upk2(unsigned long long v, float& lo, float& hi) {
    asm("mov.b64 {%0, %1}, %2;" : "=f"(lo), "=f"(hi) : "l"(v));
}
__device__ __forceinline__ unsigned long long fma2(
    unsigned long long a, unsigned long long b, unsigned long long c) {
    unsigned long long d;
    asm("fma.rn.f32x2 %0, %1, %2, %3;" : "=l"(d) : "l"(a), "l"(b), "l"(c));
    return d;
}
__device__ __forceinline__ float warpMax(float v) {
#pragma unroll
    for (int o = 16; o > 0; o >>= 1) v = fmaxf(v, __shfl_xor_sync(0xffffffffu, v, o));
    return v;
}
__device__ __forceinline__ float warpSum(float v) {
#pragma unroll
    for (int o = 16; o > 0; o >>= 1) v += __shfl_xor_sync(0xffffffffu, v, o);
    return v;
}
__device__ __forceinline__ float blockMax256(float v, float* sred) {
    v = warpMax(v);
    int w = threadIdx.x >> 5, ln = threadIdx.x & 31;
    if (ln == 0) sred[w] = v;
    __syncthreads();
    if (w == 0) {
        float x = (ln < 8) ? sred[ln] : -3.4e38f;
        x = warpMax(x);
        if (ln == 0) sred[0] = x;
    }
    __syncthreads();
    float r = sred[0];
    __syncthreads();
    return r;
}
__device__ __forceinline__ float blockSum256(float v, float* sred) {
    v = warpSum(v);
    int w = threadIdx.x >> 5, ln = threadIdx.x & 31;
    if (ln == 0) sred[w] = v;
    __syncthreads();
    if (w == 0) {
        float x = (ln < 8) ? sred[ln] : 0.f;
        x = warpSum(x);
        if (ln == 0) sred[0] = x;
    }
    __syncthreads();
    float r = sred[0];
    __syncthreads();
    return r;
}
__device__ __forceinline__ unsigned smem_u32(const void* p) {
    return (unsigned)__cvta_generic_to_shared(p);
}

// --------------------- shared GEMM body (NT, 64x128x32, f32x2) -------------
#define GBM 64
#define GBN 128
#define GBK 32
__device__ void gemm_body(const float* __restrict__ A, const float* __restrict__ B,
                          float* __restrict__ Cout, int Ncols, int bm, int bn,
                          float* As /*[32][65]*/, float* Bs /*[32][132]*/)
{
    int tid = threadIdx.x;
    int tm = (tid >> 4) * 4;
    int tn = (tid & 15) * 8;
    unsigned long long acc2[4][4];
#pragma unroll
    for (int i = 0; i < 4; ++i)
#pragma unroll
        for (int j = 0; j < 4; ++j) acc2[i][j] = 0ull;

    for (int k0 = 0; k0 < H; k0 += GBK) {
#pragma unroll
        for (int q = 0; q < 2; ++q) {
            int i = tid + q * 256;
            int m = i >> 3, f = i & 7;
            float4 v = *(const float4*)(A + (size_t)(bm + m) * H + k0 + f * 4);
            As[(f * 4 + 0) * 65 + m] = v.x; As[(f * 4 + 1) * 65 + m] = v.y;
            As[(f * 4 + 2) * 65 + m] = v.z; As[(f * 4 + 3) * 65 + m] = v.w;
        }
#pragma unroll
        for (int q = 0; q < 4; ++q) {
            int i = tid + q * 256;
            int n = i >> 3, f = i & 7;
            float4 v = *(const float4*)(B + (size_t)(bn + n) * H + k0 + f * 4);
            Bs[(f * 4 + 0) * 132 + n] = v.x; Bs[(f * 4 + 1) * 132 + n] = v.y;
            Bs[(f * 4 + 2) * 132 + n] = v.z; Bs[(f * 4 + 3) * 132 + n] = v.w;
        }
        __syncthreads();
#pragma unroll
        for (int kk = 0; kk < GBK; ++kk) {
            unsigned long long ra2[4], rb2[4];
#pragma unroll
            for (int i = 0; i < 4; ++i) {
                float a = As[kk * 65 + tm + i];
                ra2[i] = pk2(a, a);
            }
            const unsigned long long* bp = (const unsigned long long*)&Bs[kk * 132 + tn];
#pragma unroll
            for (int j = 0; j < 4; ++j) rb2[j] = bp[j];
#pragma unroll
            for (int i = 0; i < 4; ++i)
#pragma unroll
                for (int j = 0; j < 4; ++j)
                    acc2[i][j] = fma2(ra2[i], rb2[j], acc2[i][j]);
        }
        __syncthreads();
    }
#pragma unroll
    for (int i = 0; i < 4; ++i) {
        float c[8];
#pragma unroll
        for (int j = 0; j < 4; ++j) upk2(acc2[i][j], c[2 * j], c[2 * j + 1]);
        *(float4*)(Cout + (size_t)(bm + tm + i) * Ncols + bn + tn) =
            make_float4(c[0], c[1], c[2], c[3]);
        *(float4*)(Cout + (size_t)(bm + tm + i) * Ncols + bn + tn + 4) =
            make_float4(c[4], c[5], c[6], c[7]);
    }
}

// ------------- k1: start MLP + terminal MLP + transition GEMM --------------
#define TROWS 4
__global__ __launch_bounds__(256) void fused_prep(
    const float* __restrict__ se, const float* __restrict__ sw,
    const float* __restrict__ sb, const float* __restrict__ srw,
    const float* __restrict__ srb, const float* __restrict__ nse,
    const float* __restrict__ pre, const float* __restrict__ trw,
    const float* __restrict__ trb, const float* __restrict__ state)
{
    __shared__ __align__(16) float pool[6304];
    int b = blockIdx.x;
    int tid = threadIdx.x;

    if (b == 0) {
        float* x = pool;
        float* h = pool + 256;
        float* sred = pool + 512;
        x[tid] = se[tid];
        __syncthreads();
        {
            float a = sb[tid];
            for (int k0 = 0; k0 < H; k0 += 8) {
                float w[8];
#pragma unroll
                for (int u = 0; u < 8; ++u) w[u] = sw[(k0 + u) * H + tid];
#pragma unroll
                for (int u = 0; u < 8; ++u) a = fmaf(x[k0 + u], w[u], a);
            }
            __syncthreads();
            x[tid] = a;
            __syncthreads();
        }
        for (int l = 0; l < 2; ++l) {
            const float* w1 = srw + (size_t)(l * 2 + 0) * H * H;
            const float* b1 = srb + (l * 2 + 0) * H;
            const float* w2 = srw + (size_t)(l * 2 + 1) * H * H;
            const float* b2 = srb + (l * 2 + 1) * H;
            float a1 = b1[tid];
            for (int k0 = 0; k0 < H; k0 += 8) {
                float w[8];
#pragma unroll
                for (int u = 0; u < 8; ++u) w[u] = w1[(k0 + u) * H + tid];
#pragma unroll
                for (int u = 0; u < 8; ++u) a1 = fmaf(x[k0 + u], w[u], a1);
            }
            h[tid] = fmaxf(a1, 0.f);
            __syncthreads();
            float a2 = b2[tid];
            for (int k0 = 0; k0 < H; k0 += 8) {
                float w[8];
#pragma unroll
                for (int u = 0; u < 8; ++u) w[u] = w2[(k0 + u) * H + tid];
#pragma unroll
                for (int u = 0; u < 8; ++u) a2 = fmaf(h[k0 + u], w[u], a2);
            }
            __syncthreads();
            x[tid] += fmaxf(a2, 0.f);
            __syncthreads();
        }
        float l0 = 0.f, l1 = 0.f;
        const float4* r0 = (const float4*)(nse + (size_t)tid * H);
        const float4* r1 = (const float4*)(nse + (size_t)(tid + 256) * H);
        const float4* xv4 = (const float4*)x;
#pragma unroll 4
        for (int k4 = 0; k4 < H / 4; ++k4) {
            float4 xa = xv4[k4];
            float4 a = r0[k4], bb = r1[k4];
            l0 = fmaf(xa.x, a.x, l0); l0 = fmaf(xa.y, a.y, l0);
            l0 = fmaf(xa.z, a.z, l0); l0 = fmaf(xa.w, a.w, l0);
            l1 = fmaf(xa.x, bb.x, l1); l1 = fmaf(xa.y, bb.y, l1);
            l1 = fmaf(xa.z, bb.z, l1); l1 = fmaf(xa.w, bb.w, l1);
        }
        float m = blockMax256(fmaxf(l0, l1), sred);
        float e0 = expf(l0 - m), e1 = expf(l1 - m);
        float s = blockSum256(e0 + e1, sred);
        float inv = 1.f / s;
        g_startP[tid] = e0 * inv;
        g_startP[tid + 256] = e1 * inv;
    } else if (b <= 128) {
        float (*xs)[H] = (float(*)[H])pool;
        float (*hs)[H] = (float(*)[H])(pool + TROWS * H);
        int r0 = (b - 1) * TROWS;
        for (int i = tid; i < TROWS * H; i += 256)
            xs[i >> 8][i & 255] = pre[(size_t)(r0 + (i >> 8)) * H + (i & 255)];
        __syncthreads();
        for (int l = 0; l < 2; ++l) {
            const float* w1 = trw + (size_t)(l * 2 + 0) * H * H;
            const float* b1 = trb + (l * 2 + 0) * H;
            const float* w2 = trw + (size_t)(l * 2 + 1) * H * H;
            const float* b2 = trb + (l * 2 + 1) * H;
            float acc[TROWS];
#pragma unroll
            for (int r = 0; r < TROWS; ++r) acc[r] = b1[tid];
            for (int k0 = 0; k0 < H; k0 += 16) {
                float w[16];
#pragma unroll
                for (int u = 0; u < 16; ++u) w[u] = w1[(k0 + u) * H + tid];
#pragma unroll
                for (int u = 0; u < 16; ++u)
#pragma unroll
                    for (int r = 0; r < TROWS; ++r)
                        acc[r] = fmaf(xs[r][k0 + u], w[u], acc[r]);
            }
#pragma unroll
            for (int r = 0; r < TROWS; ++r) hs[r][tid] = fmaxf(acc[r], 0.f);
            __syncthreads();
#pragma unroll
            for (int r = 0; r < TROWS; ++r) acc[r] = b2[tid];
            for (int k0 = 0; k0 < H; k0 += 16) {
                float w[16];
#pragma unroll
                for (int u = 0; u < 16; ++u) w[u] = w2[(k0 + u) * H + tid];
#pragma unroll
                for (int u = 0; u < 16; ++u)
#pragma unroll
                    for (int r = 0; r < TROWS; ++r)
                        acc[r] = fmaf(hs[r][k0 + u], w[u], acc[r]);
            }
            __syncthreads();
#pragma unroll
            for (int r = 0; r < TROWS; ++r) xs[r][tid] += fmaxf(acc[r], 0.f);
            __syncthreads();
        }
        for (int i = tid; i < TROWS * H; i += 256)
            g_fe[(size_t)(r0 + (i >> 8)) * H + (i & 255)] = xs[i >> 8][i & 255];
    } else {
        int i = b - 129;
        int bn = (i & 3) * GBN;
        int bm = (i >> 2) * GBM;
        gemm_body(state, nse, g_P, C, bm, bn, pool, pool + 2080);
    }
}

// ------------- k2: transition softmax + emission GEMM ----------------------
__global__ __launch_bounds__(256) void fused_sm_gemm(
    const float* __restrict__ term)
{
    __shared__ __align__(16) float pool[6304];
    int b = blockIdx.x;
    int tid = threadIdx.x;
    if (b < C) {
        float* sred = pool;
        float* row = g_P + (size_t)b * C;
        float v0 = row[tid], v1 = row[tid + 256];
        float m = blockMax256(fmaxf(v0, v1), sred);
        float e0 = expf(v0 - m), e1 = expf(v1 - m);
        float s = blockSum256(e0 + e1, sred);
        float inv = 1.f / s;
        row[tid] = e0 * inv;
        row[tid + 256] = e1 * inv;
    } else {
        int i = b - C;
        int bn = (i % (V / GBN)) * GBN;
        int bm = (i / (V / GBN)) * GBM;
        gemm_body(g_fe, term, g_L, V, bm, bn, pool, pool + 2080);
    }
}

// ------------- k3: emission row offsets (rowmax + log sumexp) ---------------
__global__ __launch_bounds__(256) void rowstats_kernel()
{
    __shared__ float sred[32];
    int c = blockIdx.x;
    int tid = threadIdx.x;
    const float4* row = (const float4*)(g_L + (size_t)c * V);
    float mx = -3.4e38f;
    for (int i = tid; i < V / 4; i += 256) {
        float4 v = row[i];
        mx = fmaxf(mx, fmaxf(fmaxf(v.x, v.y), fmaxf(v.z, v.w)));
    }
    float m = blockMax256(mx, sred);
    float s = 0.f;
    for (int i = tid; i < V / 4; i += 256) {
        float4 v = row[i];
        s += expf(v.x - m) + expf(v.y - m) + expf(v.z - m) + expf(v.w - m);
    }
    float tot = blockSum256(s, sred);
    if (tid == 0) g_rowoff[c] = m + logf(tot);
}

// ------------------------------ k4: HMM scan -------------------------------
// 512 threads: producer tiling cp = tid&31 (2 cols), kg = tid>>5 (32-deep K).
// P2 = 32 u64 regs/thread; 4 warps/SMSP for latency hiding.
__global__ void __cluster_dims__(CLU, 1, 1) __launch_bounds__(512, 1)
scan_kernel(const int* __restrict__ text)
{
    __shared__ __align__(16) float Bf[2][CPC][C];        // 16 KB
    __shared__ __align__(16) float part[16][CPC][CSL];   // 16 KB
    __shared__ float red[CPC][CSL];
    __shared__ float inv_s[CPC];
    __shared__ float ls_s[CPC];
    __shared__ int toks[2][CPC];

    const int tid = threadIdx.x;
    const int rank = blockIdx.x & (CLU - 1);
    const int chain0 = (blockIdx.x >> 3) * CPC;
    const int c0 = rank * CSL;
    const int cp = tid & 31;       // producer: col pair (2 cols)
    const int kg = tid >> 5;       // producer: k-group (32 deep), 0..15
    const int ch = (tid >> 6) & 3; // epilogue chain (tid<256)
    const int col = tid & 63;      // epilogue column
    const int jj = tid & 31;

    // P2[k2*2+j] = {P[32kg+2k2][c0+2cp+j], P[32kg+2k2+1][c0+2cp+j]}
    unsigned long long P2[32];
#pragma unroll
    for (int k2 = 0; k2 < 16; ++k2) {
#pragma unroll
        for (int j = 0; j < 2; ++j) {
            int c = c0 + 2 * cp + j;
            float lo = g_P[(size_t)(32 * kg + 2 * k2) * C + c];
            float hi = g_P[(size_t)(32 * kg + 2 * k2 + 1) * C + c];
            P2[k2 * 2 + j] = pk2(lo, hi);
        }
    }

    if (tid < CPC) {
        toks[0][tid] = text[(chain0 + tid) * T + 0];
        toks[1][tid] = text[(chain0 + tid) * T + 1];
        ls_s[tid] = 0.f;
        inv_s[tid] = 1.f;
    }
    __syncthreads();

    // per-output emission state (tid<256: output (ch, col))
    const float* pLc = g_L + (size_t)(c0 + col) * V;
    const float offc = g_rowoff[c0 + col];

    // remote v4-store addresses (used by tid<256 with (tid&3)==0; col%4==0)
    unsigned dstD[2][CLU];
    {
        unsigned b0 = smem_u32(&Bf[0][0][0]) + (unsigned)((ch * C + c0 + col) * 4);
        unsigned b1 = smem_u32(&Bf[1][0][0]) + (unsigned)((ch * C + c0 + col) * 4);
#pragma unroll
        for (int r = 0; r < CLU; ++r) {
            asm volatile("mapa.shared::cluster.u32 %0, %1, %2;"
                         : "=r"(dstD[0][r]) : "r"(b0), "r"(r));
            asm volatile("mapa.shared::cluster.u32 %0, %1, %2;"
                         : "=r"(dstD[1][r]) : "r"(b1), "r"(r));
        }
    }

    // alpha0 into Bf[0]
    for (int i = tid; i < CPC * C; i += 512) {
        int n = i >> 9, c = i & (C - 1);
        float lv = g_L[(size_t)c * V + toks[0][n]];
        Bf[0][n][c] = g_startP[c] * __expf(lv - g_rowoff[c]);
    }
    __syncthreads();

    for (int t = 1; t < T; ++t) {
        const int rb = (t - 1) & 1, wb = t & 1;
        const bool resc = ((t & 3) == 1);

        // emission prefetch (one output column per tid<256)
        float ev = 0.f;
        if (tid < 256)
            ev = __expf(pLc[toks[wb][ch]] - offc);
        if (tid >= 508 && t + 1 < T)
            toks[(t + 1) & 1][tid - 508] = text[(chain0 + tid - 508) * T + (t + 1)];

        // deferred rescale bookkeeping every 4 steps
        if (resc) {
            if (tid < 256) {
                float mx = 0.f;
#pragma unroll
                for (int j = 0; j < 8; ++j) mx = fmaxf(mx, Bf[rb][ch][col + 64 * j]);
                red[ch][col] = mx;
            }
            __syncthreads();
            if (tid < 128) {
                int n2 = tid >> 5;
                float v = fmaxf(red[n2][jj], red[n2][jj + 32]);
                v = warpMax(v);
                if (jj == 0) { inv_s[n2] = 1.f / v; ls_s[n2] += logf(v); }
            }
            __syncthreads();
        }

        // GEMV: 2 cols x 4 chains x 32 k per thread, packed over k
#pragma unroll
        for (int c4 = 0; c4 < CPC; ++c4) {
            unsigned long long acc0 = 0ull, acc1 = 0ull;
            const ulonglong2* ap = (const ulonglong2*)&Bf[rb][c4][kg * 32];
#pragma unroll
            for (int h = 0; h < 2; ++h) {
                ulonglong2 t0 = ap[h * 4 + 0], t1 = ap[h * 4 + 1];
                ulonglong2 t2 = ap[h * 4 + 2], t3 = ap[h * 4 + 3];
                unsigned long long av[8] = { t0.x, t0.y, t1.x, t1.y,
                                             t2.x, t2.y, t3.x, t3.y };
#pragma unroll
                for (int k2 = 0; k2 < 8; ++k2) {
                    acc0 = fma2(av[k2], P2[(h * 8 + k2) * 2 + 0], acc0);
                    acc1 = fma2(av[k2], P2[(h * 8 + k2) * 2 + 1], acc1);
                }
            }
            float lo, hi;
            float2 v;
            upk2(acc0, lo, hi); v.x = lo + hi;
            upk2(acc1, lo, hi); v.y = lo + hi;
            *(float2*)&part[kg][c4][2 * cp] = v;
        }
        __syncthreads();

        // epilogue: tid<256, one output (ch, col) each
        if (tid < 256) {
            float p[16];
#pragma unroll
            for (int q = 0; q < 16; ++q) p[q] = part[q][ch][col];
            float s = (((p[0] + p[1]) + (p[2] + p[3])) +
                       ((p[4] + p[5]) + (p[6] + p[7]))) +
                      (((p[8] + p[9]) + (p[10] + p[11])) +
                       ((p[12] + p[13]) + (p[14] + p[15])));
            const float inv = resc ? inv_s[ch] : 1.f;
            float val = s * (ev * inv);
            float v1 = __shfl_down_sync(0xffffffffu, val, 1);
            float v2 = __shfl_down_sync(0xffffffffu, val, 2);
            float v3 = __shfl_down_sync(0xffffffffu, val, 3);
            if ((tid & 3) == 0) {
#pragma unroll
                for (int r = 0; r < CLU; ++r)
                    asm volatile("st.shared::cluster.v4.b32 [%0], {%1, %2, %3, %4};"
                                 :: "r"(dstD[wb][r]), "f"(val), "f"(v1),
                                    "f"(v2), "f"(v3) : "memory");
            }
        }
        asm volatile("barrier.cluster.arrive.aligned;" ::: "memory");
        asm volatile("barrier.cluster.wait.aligned;" ::: "memory");
    }

    // final: logZ[n] = ls[n] + log(sum_c Bf[(T-1)&1][n][c])
    {
        if (tid < 256) {
            float sm = 0.f;
#pragma unroll
            for (int j = 0; j < 8; ++j) sm += Bf[(T - 1) & 1][ch][col + 64 * j];
            red[ch][col] = sm;
        }
        __syncthreads();
        if (tid < 128) {
            int n2 = tid >> 5;
            float v = red[n2][jj] + red[n2][jj + 32];
            v = warpSum(v);
            if (jj == 0 && rank == 0)
                g_logZ[chain0 + n2] = ls_s[n2] + logf(v);
        }
    }
}

__global__ void final_sum_kernel(float* __restrict__ out)
{
    __shared__ float s[64];
    int tid = threadIdx.x;
    s[tid] = g_logZ[tid];
    __syncthreads();
#pragma unroll
    for (int o = 32; o > 0; o >>= 1) {
        if (tid < o) s[tid] += s[tid + o];
        __syncthreads();
    }
    if (tid == 0) out[0] = s[0];
}

extern "C" void kernel_launch(void* const* d_in, const int* in_sizes, int n_in,
                              void* d_out, int out_size)
{
    const int*   text  = (const int*)  d_in[0];
    const float* se    = (const float*)d_in[1];
    const float* sw    = (const float*)d_in[2];
    const float* sb    = (const float*)d_in[3];
    const float* srw   = (const float*)d_in[4];
    const float* srb   = (const float*)d_in[5];
    const float* state = (const float*)d_in[6];
    const float* nse   = (const float*)d_in[7];
    const float* pre   = (const float*)d_in[8];
    const float* trw   = (const float*)d_in[9];
    const float* trb   = (const float*)d_in[10];
    const float* term  = (const float*)d_in[11];
    float* out = (float*)d_out;

    fused_prep<<<1 + 128 + 32, 256>>>(se, sw, sb, srw, srb, nse,
                                      pre, trw, trb, state);
    fused_sm_gemm<<<C + (V / GBN) * (C / GBM), 256>>>(term);
    rowstats_kernel<<<C, 256>>>();
    scan_kernel<<<(NB / CPC) * CLU, 512>>>(text);
    final_sum_kernel<<<1, 64>>>(out);
}